// round 2
// baseline (speedup 1.0000x reference)
#include <cuda_runtime.h>
#include <math.h>

// Problem dims (fixed per reference)
#define Bdim 32
#define Sdim 2048
#define Ddim 1024
#define Udim 1024
#define BS   (Bdim * Sdim)   // 65536 rows of the big GEMM

// ---- scratch (no cudaMalloc allowed) ----
__device__ float g_dec_p[Bdim * Udim];          // [B,U]
__device__ float g_scores[Bdim * Sdim];         // [B,S]
__device__ float g_wpart[4 * Bdim * Ddim];      // 4 s-split partials of attn-weighted h_enc

// ---- packed f32x2 helpers (Blackwell FFMA2 only reachable via PTX) ----
__device__ __forceinline__ unsigned long long pack2(float x, float y) {
    unsigned long long r;
    asm("mov.b64 %0, {%1, %2};" : "=l"(r) : "f"(x), "f"(y));
    return r;
}
__device__ __forceinline__ unsigned long long dup2(float x) {
    unsigned long long r;
    asm("mov.b64 %0, {%1, %2};" : "=l"(r) : "f"(x), "f"(x));
    return r;
}
__device__ __forceinline__ unsigned long long ffma2(unsigned long long a, unsigned long long b,
                                                    unsigned long long c) {
    unsigned long long d;
    asm("fma.rn.f32x2 %0, %1, %2, %3;" : "=l"(d) : "l"(a), "l"(b), "l"(c));
    return d;
}
__device__ __forceinline__ void unpack2(unsigned long long v, float& x, float& y) {
    asm("mov.b64 {%0, %1}, %2;" : "=f"(x), "=f"(y) : "l"(v));
}

// ============================================================================
// Kernel 1: dec_p[b,u] = b_dec[u] + sum_d h_dec[b,d] * W_dec[d,u]
// grid (B, U/256), 256 threads
// ============================================================================
__global__ __launch_bounds__(256) void decp_kernel(const float* __restrict__ h_dec,
                                                   const float* __restrict__ W_dec,
                                                   const float* __restrict__ b_dec) {
    __shared__ float hv[Ddim];
    const int b = blockIdx.x;
    const int u = blockIdx.y * 256 + threadIdx.x;
    for (int d = threadIdx.x; d < Ddim; d += 256) hv[d] = h_dec[b * Ddim + d];
    __syncthreads();
    float acc = b_dec[u];
    #pragma unroll 8
    for (int d = 0; d < Ddim; ++d) acc = fmaf(hv[d], W_dec[d * Udim + u], acc);
    g_dec_p[b * Udim + u] = acc;
}

// ============================================================================
// Kernel 2: fused score GEMM.
// scores[row] = b_com + sum_u W_com[u] * tanh(dec_p[b,u] + (h_enc_row . W_enc[:,u]))
// Tiling: block = 128 rows; loops 8 N-tiles of 128 over U; K=1024 in 32-chunks.
// 256 threads, each an 8x8 microtile, accumulators packed (pairs along M) for FFMA2.
// ============================================================================
#define BM 128
#define BN 128
#define BK 32
#define SSTR 132   // smem row stride (floats), 16B-aligned, reduces conflicts

__global__ __launch_bounds__(256, 1) void score_kernel(const float* __restrict__ A,      // h_enc flat [BS,D]
                                                       const float* __restrict__ Bm,     // W_enc [D,U]
                                                       const float* __restrict__ W_com,
                                                       const float* __restrict__ b_com) {
    __shared__ float As[BK][SSTR];   // transposed: As[k][m]
    __shared__ float Bs[BK][SSTR];   // Bs[k][n]
    __shared__ float red[BM][17];

    const int tid = threadIdx.x;
    const int tm = tid >> 4;    // 0..15 -> rows tm*8..+7
    const int tn = tid & 15;    // 0..15 -> cols tn*8..+7
    const int row0 = blockIdx.x * BM;
    const int b = row0 >> 11;   // 2048 rows per batch, BM divides 2048

    float sp[8];
    #pragma unroll
    for (int i = 0; i < 8; ++i) sp[i] = 0.f;

    #pragma unroll 1
    for (int nt = 0; nt < Udim / BN; ++nt) {
        const int n0 = nt * BN;
        unsigned long long c[4][8];   // c[mpair][n]: rows tm*8+2i, tm*8+2i+1
        #pragma unroll
        for (int i = 0; i < 4; ++i)
            #pragma unroll
            for (int j = 0; j < 8; ++j) c[i][j] = 0ull;

        #pragma unroll 1
        for (int kt = 0; kt < Ddim; kt += BK) {
            // --- load A tile transposed: 128 rows x 32 k ---
            #pragma unroll
            for (int v = 0; v < 4; ++v) {
                int f = tid + v * 256;        // float4 index 0..1023
                int r = f >> 3;               // row 0..127
                int kq = f & 7;               // float4 within 32-k row
                float4 av = *reinterpret_cast<const float4*>(A + (size_t)(row0 + r) * Ddim + kt + kq * 4);
                As[kq * 4 + 0][r] = av.x;
                As[kq * 4 + 1][r] = av.y;
                As[kq * 4 + 2][r] = av.z;
                As[kq * 4 + 3][r] = av.w;
            }
            // --- load B tile: 32 k x 128 n ---
            #pragma unroll
            for (int v = 0; v < 4; ++v) {
                int f = tid + v * 256;
                int k = f >> 5;               // 0..31
                int nq = f & 31;              // float4 within 128-n row
                *reinterpret_cast<float4*>(&Bs[k][nq * 4]) =
                    *reinterpret_cast<const float4*>(Bm + (size_t)(kt + k) * Udim + n0 + nq * 4);
            }
            __syncthreads();

            #pragma unroll
            for (int k = 0; k < BK; ++k) {
                float4 a0 = *reinterpret_cast<const float4*>(&As[k][tm * 8]);
                float4 a1 = *reinterpret_cast<const float4*>(&As[k][tm * 8 + 4]);
                float4 b0 = *reinterpret_cast<const float4*>(&Bs[k][tn * 8]);
                float4 b1 = *reinterpret_cast<const float4*>(&Bs[k][tn * 8 + 4]);
                unsigned long long ap[4];
                ap[0] = pack2(a0.x, a0.y);
                ap[1] = pack2(a0.z, a0.w);
                ap[2] = pack2(a1.x, a1.y);
                ap[3] = pack2(a1.z, a1.w);
                unsigned long long bd[8];
                bd[0] = dup2(b0.x); bd[1] = dup2(b0.y); bd[2] = dup2(b0.z); bd[3] = dup2(b0.w);
                bd[4] = dup2(b1.x); bd[5] = dup2(b1.y); bd[6] = dup2(b1.z); bd[7] = dup2(b1.w);
                #pragma unroll
                for (int i = 0; i < 4; ++i)
                    #pragma unroll
                    for (int j = 0; j < 8; ++j)
                        c[i][j] = ffma2(ap[i], bd[j], c[i][j]);
            }
            __syncthreads();
        }

        // --- epilogue for this n-tile: tanh + W_com reduction into row partials ---
        const float* dp = g_dec_p + b * Udim + n0 + tn * 8;
        const float* wc = W_com + n0 + tn * 8;
        #pragma unroll
        for (int j = 0; j < 8; ++j) {
            float d = dp[j];
            float w = wc[j];
            #pragma unroll
            for (int i = 0; i < 4; ++i) {
                float x, y;
                unpack2(c[i][j], x, y);
                sp[2 * i + 0] += w * tanhf(x + d);
                sp[2 * i + 1] += w * tanhf(y + d);
            }
        }
    }

    // reduce across the 16 tn-threads sharing each row
    #pragma unroll
    for (int i = 0; i < 8; ++i) red[tm * 8 + i][tn] = sp[i];
    __syncthreads();
    if (tid < BM) {
        float s = b_com[0];
        #pragma unroll
        for (int t = 0; t < 16; ++t) s += red[tid][t];
        g_scores[row0 + tid] = s;
    }
}

// ============================================================================
// Kernel 3: softmax over S per batch. grid (B), 256 threads, 8 elems/thread.
// Writes attn directly into d_out's attn section.
// ============================================================================
__global__ __launch_bounds__(256) void softmax_kernel(float* __restrict__ attn_out) {
    __shared__ float sm[256];
    const int b = blockIdx.x;
    const int tid = threadIdx.x;
    float v[8];
    float mx = -3.4e38f;
    #pragma unroll
    for (int i = 0; i < 8; ++i) {
        v[i] = g_scores[b * Sdim + tid + i * 256];
        mx = fmaxf(mx, v[i]);
    }
    sm[tid] = mx;
    __syncthreads();
    for (int off = 128; off > 0; off >>= 1) {
        if (tid < off) sm[tid] = fmaxf(sm[tid], sm[tid + off]);
        __syncthreads();
    }
    const float m = sm[0];
    __syncthreads();
    float sum = 0.f;
    #pragma unroll
    for (int i = 0; i < 8; ++i) {
        v[i] = expf(v[i] - m);
        sum += v[i];
    }
    sm[tid] = sum;
    __syncthreads();
    for (int off = 128; off > 0; off >>= 1) {
        if (tid < off) sm[tid] += sm[tid + off];
        __syncthreads();
    }
    const float inv = 1.f / sm[0];
    #pragma unroll
    for (int i = 0; i < 8; ++i) attn_out[b * Sdim + tid + i * 256] = v[i] * inv;
}

// ============================================================================
// Kernel 4: weighted[b,d] = sum_s attn[b,s] * h_enc[b,s,d], s split 4 ways.
// grid (B, D/256, 4), 256 threads. BW-bound: streams 256 MB.
// ============================================================================
__global__ __launch_bounds__(256) void weighted_kernel(const float* __restrict__ h_enc,
                                                       const float* __restrict__ attn) {
    const int b = blockIdx.x;
    const int d = blockIdx.y * 256 + threadIdx.x;
    const int spl = blockIdx.z;
    const int s0 = spl * (Sdim / 4);
    const float* base = h_enc + ((size_t)b * Sdim + s0) * Ddim + d;
    const float* av = attn + b * Sdim + s0;
    float acc = 0.f;
    #pragma unroll 8
    for (int s = 0; s < Sdim / 4; ++s) acc = fmaf(__ldg(av + s), base[(size_t)s * Ddim], acc);
    g_wpart[(spl * Bdim + b) * Ddim + d] = acc;
}

// ============================================================================
// Kernel 5: context[b,u] = b_enc[u] + sum_d weighted[b,d] * W_enc[d,u]
// grid (B, U/256), 256 threads.
// ============================================================================
__global__ __launch_bounds__(256) void context_kernel(const float* __restrict__ W_enc,
                                                      const float* __restrict__ b_enc,
                                                      float* __restrict__ out_ctx) {
    __shared__ float wv[Ddim];
    const int b = blockIdx.x;
    const int u = blockIdx.y * 256 + threadIdx.x;
    for (int d = threadIdx.x; d < Ddim; d += 256) {
        wv[d] = g_wpart[(0 * Bdim + b) * Ddim + d] + g_wpart[(1 * Bdim + b) * Ddim + d] +
                g_wpart[(2 * Bdim + b) * Ddim + d] + g_wpart[(3 * Bdim + b) * Ddim + d];
    }
    __syncthreads();
    float acc = b_enc[u];
    #pragma unroll 8
    for (int d = 0; d < Ddim; ++d) acc = fmaf(wv[d], W_enc[d * Udim + u], acc);
    out_ctx[b * Udim + u] = acc;
}

// ============================================================================
extern "C" void kernel_launch(void* const* d_in, const int* in_sizes, int n_in,
                              void* d_out, int out_size) {
    const float* h_enc = (const float*)d_in[0];
    const float* h_dec = (const float*)d_in[1];
    const float* W_enc = (const float*)d_in[2];
    const float* b_enc = (const float*)d_in[3];
    const float* W_dec = (const float*)d_in[4];
    const float* b_dec = (const float*)d_in[5];
    const float* W_com = (const float*)d_in[6];
    const float* b_com = (const float*)d_in[7];

    float* out = (float*)d_out;
    float* out_ctx = out;                    // [B,U]  = 32768 floats
    float* out_attn = out + Bdim * Udim;     // [B,S,1] = 65536 floats

    decp_kernel<<<dim3(Bdim, Udim / 256), 256>>>(h_dec, W_dec, b_dec);
    score_kernel<<<BS / BM, 256>>>(h_enc, W_enc, W_com, b_com);
    softmax_kernel<<<Bdim, 256>>>(out_attn);
    weighted_kernel<<<dim3(Bdim, Ddim / 256, 4), 256>>>(h_enc, out_attn);
    context_kernel<<<dim3(Bdim, Udim / 256), 256>>>(W_enc, b_enc, out_ctx);
}

// round 9
// speedup vs baseline: 2.1794x; 2.1794x over previous
#include <cuda_runtime.h>
#include <cuda_bf16.h>
#include <math.h>
#include <stdint.h>

// Problem dims (fixed per reference)
#define Bdim 32
#define Sdim 2048
#define Ddim 1024
#define Udim 1024
#define BS   (Bdim * Sdim)   // 65536 rows of the big GEMM

// ---- device scratch (no cudaMalloc allowed) ----
__device__ float g_dec_p[Bdim * Udim];            // [B,U]
__device__ float g_scores[Bdim * Sdim];           // [B,S]
__device__ float g_wpart[8 * Bdim * Ddim];        // s-split partials of attn-weighted h_enc
__device__ __nv_bfloat16 g_Ahi[(size_t)BS * Ddim];   // h_enc hi  (128MB)
__device__ __nv_bfloat16 g_Alo[(size_t)BS * Ddim];   // h_enc lo  (128MB)
__device__ __nv_bfloat16 g_Bhi[(size_t)Udim * Ddim]; // W_enc^T hi [u][d]
__device__ __nv_bfloat16 g_Blo[(size_t)Udim * Ddim]; // W_enc^T lo [u][d]

// ============================================================================
// PTX helpers (portable: sm_80-level ISA only — cp.async / ldmatrix / mma.sync)
// ============================================================================
__device__ __forceinline__ uint32_t smem_to_u32(const void* p) {
    uint32_t a;
    asm("{ .reg .u64 t; cvta.to.shared.u64 t, %1; cvt.u32.u64 %0, t; }" : "=r"(a) : "l"(p));
    return a;
}
#define CP_ASYNC16(dst, src) \
    asm volatile("cp.async.cg.shared.global [%0], [%1], 16;" :: "r"(dst), "l"(src) : "memory")
#define CP_COMMIT() asm volatile("cp.async.commit_group;" ::: "memory")
#define CP_WAIT1()  asm volatile("cp.async.wait_group 1;" ::: "memory")
#define CP_WAIT0()  asm volatile("cp.async.wait_group 0;" ::: "memory")

__device__ __forceinline__ void ldsm4(uint32_t* r, uint32_t addr) {
    asm volatile("ldmatrix.sync.aligned.m8n8.x4.shared.b16 {%0,%1,%2,%3}, [%4];"
                 : "=r"(r[0]), "=r"(r[1]), "=r"(r[2]), "=r"(r[3]) : "r"(addr));
}
// D(f32) += A(bf16,4regs) * B(bf16,2regs)   m16n8k16 row.col
__device__ __forceinline__ void mma_bf16(float* d, const uint32_t* a, uint32_t b0, uint32_t b1) {
    asm volatile(
        "mma.sync.aligned.m16n8k16.row.col.f32.bf16.bf16.f32 "
        "{%0,%1,%2,%3}, {%4,%5,%6,%7}, {%8,%9}, {%0,%1,%2,%3};"
        : "+f"(d[0]), "+f"(d[1]), "+f"(d[2]), "+f"(d[3])
        : "r"(a[0]), "r"(a[1]), "r"(a[2]), "r"(a[3]), "r"(b0), "r"(b1));
}

// fast fp32 tanh (Eigen/XLA rational 13/6, ~1e-7 core error)
__device__ __forceinline__ float tanh_fast(float x) {
    float xc = fminf(fmaxf(x, -7.99f), 7.99f);
    float x2 = xc * xc;
    float p = -2.76076847742355e-16f;
    p = fmaf(p, x2, 2.00018790482477e-13f);
    p = fmaf(p, x2, -8.60467152213735e-11f);
    p = fmaf(p, x2, 5.12229709037114e-08f);
    p = fmaf(p, x2, 1.48572235717979e-05f);
    p = fmaf(p, x2, 6.37261928875436e-04f);
    p = fmaf(p, x2, 4.89352455891786e-03f);
    p = p * xc;
    float q = 1.19825839466702e-06f;
    q = fmaf(q, x2, 1.18534705686654e-04f);
    q = fmaf(q, x2, 2.26843463243900e-03f);
    q = fmaf(q, x2, 4.89352518554385e-03f);
    return __fdividef(p, q);
}

// ============================================================================
// Kernel 0a: convert h_enc -> bf16 hi/lo (same layout)
// ============================================================================
__global__ __launch_bounds__(256) void conv_h_kernel(const float* __restrict__ src) {
    size_t i = ((size_t)blockIdx.x * 256 + threadIdx.x) * 4;
    float4 v = *reinterpret_cast<const float4*>(src + i);
    __nv_bfloat16 h0 = __float2bfloat16(v.x), h1 = __float2bfloat16(v.y);
    __nv_bfloat16 h2 = __float2bfloat16(v.z), h3 = __float2bfloat16(v.w);
    __nv_bfloat16 l0 = __float2bfloat16(v.x - __bfloat162float(h0));
    __nv_bfloat16 l1 = __float2bfloat16(v.y - __bfloat162float(h1));
    __nv_bfloat16 l2 = __float2bfloat16(v.z - __bfloat162float(h2));
    __nv_bfloat16 l3 = __float2bfloat16(v.w - __bfloat162float(h3));
    *reinterpret_cast<__nv_bfloat162*>(g_Ahi + i)     = __halves2bfloat162(h0, h1);
    *reinterpret_cast<__nv_bfloat162*>(g_Ahi + i + 2) = __halves2bfloat162(h2, h3);
    *reinterpret_cast<__nv_bfloat162*>(g_Alo + i)     = __halves2bfloat162(l0, l1);
    *reinterpret_cast<__nv_bfloat162*>(g_Alo + i + 2) = __halves2bfloat162(l2, l3);
}

// ============================================================================
// Kernel 0b: W_enc [D,U] -> transposed bf16 hi/lo [U,D]
// ============================================================================
__global__ __launch_bounds__(256) void conv_w_kernel(const float* __restrict__ W) {
    __shared__ float s[32][33];
    int tx = threadIdx.x, ty = threadIdx.y;     // 32 x 8
    int u0 = blockIdx.x * 32, d0 = blockIdx.y * 32;
    #pragma unroll
    for (int k = 0; k < 4; ++k)
        s[ty + k * 8][tx] = W[(size_t)(d0 + ty + k * 8) * Udim + u0 + tx];
    __syncthreads();
    #pragma unroll
    for (int k = 0; k < 4; ++k) {
        float v = s[tx][ty + k * 8];
        __nv_bfloat16 hi = __float2bfloat16(v);
        __nv_bfloat16 lo = __float2bfloat16(v - __bfloat162float(hi));
        size_t o = (size_t)(u0 + ty + k * 8) * Ddim + d0 + tx;
        g_Bhi[o] = hi;
        g_Blo[o] = lo;
    }
}

// ============================================================================
// Kernel 1: dec_p[b,u] = b_dec[u] + sum_d h_dec[b,d] * W_dec[d,u]
// ============================================================================
__global__ __launch_bounds__(256) void decp_kernel(const float* __restrict__ h_dec,
                                                   const float* __restrict__ W_dec,
                                                   const float* __restrict__ b_dec) {
    __shared__ float hv[Ddim];
    const int b = blockIdx.x;
    const int u = blockIdx.y * 256 + threadIdx.x;
    for (int d = threadIdx.x; d < Ddim; d += 256) hv[d] = h_dec[b * Ddim + d];
    __syncthreads();
    float acc = b_dec[u];
    #pragma unroll 8
    for (int d = 0; d < Ddim; ++d) acc = fmaf(hv[d], W_dec[d * Udim + u], acc);
    g_dec_p[b * Udim + u] = acc;
}

// ============================================================================
// Kernel 2: score GEMM via mma.sync bf16 (3-product split) + fused epilogue.
// CTA 128 rows x 128 cols/n-group, 8 n-groups over U. 8 warps: warp = 32m x 64n.
// BK=32, 2-stage cp.async. Smem rows padded to 40 bf16 (80B) -> ldmatrix
// conflict-free (16B-group = 5r+s mod 8).
// ============================================================================
#define ASTRIDE  40u                    // bf16 elems per smem row (80 bytes)
#define MAT_BYTES 10240u                // 128 rows * 80B, one (hi|lo) matrix
#define STG_BYTES 20480u                // hi+lo per stage
#define OFF_A    0u                     // 2 stages -> 40960
#define OFF_B    40960u                 // 2 stages -> 40960
#define OFF_DECW 81920u                 // float2[1024] = 8192
#define OFF_RED  90112u                 // float[128][2] = 1024
#define SMEM_SCORE 91136u

__device__ __forceinline__ void score_loads(int stage, int kt, int ng, int tid, int row0,
                                            uint32_t sbase) {
    #pragma unroll
    for (int k = 0; k < 4; ++k) {                 // A: 1024 chunks of 16B
        int idx = tid + k * 256;
        int h = idx >> 9, r = (idx >> 2) & 127, seg = idx & 3;
        const __nv_bfloat16* src =
            (h ? g_Alo : g_Ahi) + (((size_t)(row0 + r)) << 10) + (kt << 5) + (seg << 3);
        uint32_t dst = sbase + OFF_A + (uint32_t)stage * STG_BYTES + (uint32_t)h * MAT_BYTES +
                       (uint32_t)(r * 80 + seg * 16);
        CP_ASYNC16(dst, src);
    }
    const int u0 = ng * 128;
    #pragma unroll
    for (int k = 0; k < 4; ++k) {                 // B
        int idx = tid + k * 256;
        int h = idx >> 9, r = (idx >> 2) & 127, seg = idx & 3;
        const __nv_bfloat16* src =
            (h ? g_Blo : g_Bhi) + (((size_t)(u0 + r)) << 10) + (kt << 5) + (seg << 3);
        uint32_t dst = sbase + OFF_B + (uint32_t)stage * STG_BYTES + (uint32_t)h * MAT_BYTES +
                       (uint32_t)(r * 80 + seg * 16);
        CP_ASYNC16(dst, src);
    }
}

__global__ __launch_bounds__(256) void score_mma_kernel(const float* __restrict__ W_com,
                                                        const float* __restrict__ b_com,
                                                        const float* __restrict__ b_enc) {
    extern __shared__ char sm[];
    const uint32_t sbase = smem_to_u32(sm);
    float2* decw = reinterpret_cast<float2*>(sm + OFF_DECW);
    float* red   = reinterpret_cast<float*>(sm + OFF_RED);

    const int tid  = threadIdx.x;
    const int wid  = tid >> 5, lane = tid & 31;
    const int wm   = wid >> 1;          // 0..3 -> rows wm*32
    const int wn   = wid & 1;           // 0..1 -> cols wn*64
    const int row0 = blockIdx.x * 128;
    const int b    = row0 >> 11;

    for (int i = tid; i < Udim; i += 256)
        decw[i] = make_float2(g_dec_p[b * Udim + i] + b_enc[i], W_com[i]);
    __syncthreads();

    float rs[4] = {0.f, 0.f, 0.f, 0.f};
    const uint32_t lrow = (uint32_t)(lane & 15) * 80u + ((uint32_t)(lane >> 4) << 4);

    #pragma unroll 1
    for (int ng = 0; ng < 8; ++ng) {
        float acc[2][8][4];
        #pragma unroll
        for (int mi = 0; mi < 2; ++mi)
            #pragma unroll
            for (int nj = 0; nj < 8; ++nj)
                #pragma unroll
                for (int e = 0; e < 4; ++e) acc[mi][nj][e] = 0.f;

        score_loads(0, 0, ng, tid, row0, sbase);
        CP_COMMIT();

        #pragma unroll 1
        for (int kt = 0; kt < 32; ++kt) {
            if (kt < 31) {
                score_loads((kt + 1) & 1, kt + 1, ng, tid, row0, sbase);
                CP_COMMIT();
                CP_WAIT1();
            } else {
                CP_WAIT0();
            }
            __syncthreads();

            const uint32_t aB = sbase + OFF_A + (uint32_t)(kt & 1) * STG_BYTES;
            const uint32_t bB = sbase + OFF_B + (uint32_t)(kt & 1) * STG_BYTES;
            #pragma unroll
            for (int ks = 0; ks < 2; ++ks) {
                uint32_t ah[2][4], al[2][4];
                uint32_t aaddr = aB + (uint32_t)(wm * 32) * 80u + lrow + (uint32_t)ks * 32u;
                ldsm4(ah[0], aaddr);
                ldsm4(ah[1], aaddr + 16u * 80u);
                ldsm4(al[0], aaddr + MAT_BYTES);
                ldsm4(al[1], aaddr + MAT_BYTES + 16u * 80u);
                #pragma unroll
                for (int p = 0; p < 4; ++p) {
                    uint32_t baddr = bB + (uint32_t)(wn * 64 + p * 16) * 80u + lrow +
                                     (uint32_t)ks * 32u;
                    uint32_t bh[4], bl[4];
                    ldsm4(bh, baddr);
                    ldsm4(bl, baddr + MAT_BYTES);
                    // hi*hi
                    mma_bf16(acc[0][2 * p],     ah[0], bh[0], bh[2]);
                    mma_bf16(acc[0][2 * p + 1], ah[0], bh[1], bh[3]);
                    mma_bf16(acc[1][2 * p],     ah[1], bh[0], bh[2]);
                    mma_bf16(acc[1][2 * p + 1], ah[1], bh[1], bh[3]);
                    // lo*hi
                    mma_bf16(acc[0][2 * p],     al[0], bh[0], bh[2]);
                    mma_bf16(acc[0][2 * p + 1], al[0], bh[1], bh[3]);
                    mma_bf16(acc[1][2 * p],     al[1], bh[0], bh[2]);
                    mma_bf16(acc[1][2 * p + 1], al[1], bh[1], bh[3]);
                    // hi*lo
                    mma_bf16(acc[0][2 * p],     ah[0], bl[0], bl[2]);
                    mma_bf16(acc[0][2 * p + 1], ah[0], bl[1], bl[3]);
                    mma_bf16(acc[1][2 * p],     ah[1], bl[0], bl[2]);
                    mma_bf16(acc[1][2 * p + 1], ah[1], bl[1], bl[3]);
                }
            }
            __syncthreads();
        }

        // epilogue: x = enc_p + (dec_p + b_enc); rs += W_com * tanh(x)
        #pragma unroll
        for (int mi = 0; mi < 2; ++mi) {
            #pragma unroll
            for (int nj = 0; nj < 8; ++nj) {
                int u = ng * 128 + wn * 64 + nj * 8 + 2 * (lane & 3);
                float2 w0 = decw[u];
                float2 w1 = decw[u + 1];
                rs[2 * mi] += w0.y * tanh_fast(acc[mi][nj][0] + w0.x) +
                              w1.y * tanh_fast(acc[mi][nj][1] + w1.x);
                rs[2 * mi + 1] += w0.y * tanh_fast(acc[mi][nj][2] + w0.x) +
                                  w1.y * tanh_fast(acc[mi][nj][3] + w1.x);
            }
        }
    }

    // reduce the 4-lane quads that share a row
    #pragma unroll
    for (int i = 0; i < 4; ++i) {
        rs[i] += __shfl_xor_sync(0xffffffffu, rs[i], 1);
        rs[i] += __shfl_xor_sync(0xffffffffu, rs[i], 2);
    }
    if ((lane & 3) == 0) {
        #pragma unroll
        for (int mi = 0; mi < 2; ++mi)
            #pragma unroll
            for (int h = 0; h < 2; ++h) {
                int row = wm * 32 + mi * 16 + h * 8 + (lane >> 2);
                red[row * 2 + wn] = rs[2 * mi + h];
            }
    }
    __syncthreads();
    if (tid < 128)
        g_scores[row0 + tid] = red[tid * 2] + red[tid * 2 + 1] + __ldg(&b_com[0]);
}

// ============================================================================
// Kernel 3: softmax over S per batch
// ============================================================================
__global__ __launch_bounds__(256) void softmax_kernel(float* __restrict__ attn_out) {
    __shared__ float sm[256];
    const int b = blockIdx.x;
    const int tid = threadIdx.x;
    float v[8];
    float mx = -3.4e38f;
    #pragma unroll
    for (int i = 0; i < 8; ++i) {
        v[i] = g_scores[b * Sdim + tid + i * 256];
        mx = fmaxf(mx, v[i]);
    }
    sm[tid] = mx;
    __syncthreads();
    for (int off = 128; off > 0; off >>= 1) {
        if (tid < off) sm[tid] = fmaxf(sm[tid], sm[tid + off]);
        __syncthreads();
    }
    const float m = sm[0];
    __syncthreads();
    float sum = 0.f;
    #pragma unroll
    for (int i = 0; i < 8; ++i) {
        v[i] = expf(v[i] - m);
        sum += v[i];
    }
    sm[tid] = sum;
    __syncthreads();
    for (int off = 128; off > 0; off >>= 1) {
        if (tid < off) sm[tid] += sm[tid + off];
        __syncthreads();
    }
    const float inv = 1.f / sm[0];
    #pragma unroll
    for (int i = 0; i < 8; ++i) attn_out[b * Sdim + tid + i * 256] = v[i] * inv;
}

// ============================================================================
// Kernel 4: weighted[b,d] = sum_s attn[b,s] * h_enc[b,s,d]  (8 s-splits)
// ============================================================================
__global__ __launch_bounds__(256) void weighted_kernel(const float* __restrict__ h_enc,
                                                       const float* __restrict__ attn) {
    const int b = blockIdx.x;
    const int d = blockIdx.y * 256 + threadIdx.x;
    const int spl = blockIdx.z;
    const int s0 = spl * (Sdim / 8);
    const float* base = h_enc + ((size_t)b * Sdim + s0) * Ddim + d;
    const float* av = attn + b * Sdim + s0;
    float acc = 0.f;
    #pragma unroll 8
    for (int s = 0; s < Sdim / 8; ++s) acc = fmaf(__ldg(av + s), base[(size_t)s * Ddim], acc);
    g_wpart[(spl * Bdim + b) * Ddim + d] = acc;
}

// ============================================================================
// Kernel 5: context[b,u] = b_enc[u] + sum_d weighted[b,d] * W_enc[d,u]
// ============================================================================
__global__ __launch_bounds__(256) void context_kernel(const float* __restrict__ W_enc,
                                                      const float* __restrict__ b_enc,
                                                      float* __restrict__ out_ctx) {
    __shared__ float wv[Ddim];
    const int b = blockIdx.x;
    const int u = blockIdx.y * 256 + threadIdx.x;
    for (int d = threadIdx.x; d < Ddim; d += 256) {
        float s = 0.f;
        #pragma unroll
        for (int p = 0; p < 8; ++p) s += g_wpart[(p * Bdim + b) * Ddim + d];
        wv[d] = s;
    }
    __syncthreads();
    float acc = b_enc[u];
    #pragma unroll 8
    for (int d = 0; d < Ddim; ++d) acc = fmaf(wv[d], W_enc[d * Udim + u], acc);
    out_ctx[b * Udim + u] = acc;
}

// ============================================================================
extern "C" void kernel_launch(void* const* d_in, const int* in_sizes, int n_in,
                              void* d_out, int out_size) {
    const float* h_enc = (const float*)d_in[0];
    const float* h_dec = (const float*)d_in[1];
    const float* W_enc = (const float*)d_in[2];
    const float* b_enc = (const float*)d_in[3];
    const float* W_dec = (const float*)d_in[4];
    const float* b_dec = (const float*)d_in[5];
    const float* W_com = (const float*)d_in[6];
    const float* b_com = (const float*)d_in[7];

    float* out = (float*)d_out;
    float* out_ctx = out;                 // [B,U]
    float* out_attn = out + Bdim * Udim;  // [B,S,1]

    cudaFuncSetAttribute(score_mma_kernel, cudaFuncAttributeMaxDynamicSharedMemorySize,
                         SMEM_SCORE);

    conv_h_kernel<<<(BS * Ddim) / (256 * 4), 256>>>(h_enc);
    conv_w_kernel<<<dim3(Udim / 32, Ddim / 32), dim3(32, 8)>>>(W_enc);
    decp_kernel<<<dim3(Bdim, Udim / 256), 256>>>(h_dec, W_dec, b_dec);
    score_mma_kernel<<<BS / 128, 256, SMEM_SCORE>>>(W_com, b_com, b_enc);
    softmax_kernel<<<Bdim, 256>>>(out_attn);
    weighted_kernel<<<dim3(Bdim, Ddim / 256, 8), 256>>>(h_enc, out_attn);
    context_kernel<<<dim3(Bdim, Udim / 256), 256>>>(W_enc, b_enc, out_ctx);
}

// round 10
// speedup vs baseline: 2.9239x; 1.3416x over previous
#include <cuda_runtime.h>
#include <cuda_fp16.h>
#include <math.h>
#include <stdint.h>

// Problem dims (fixed per reference)
#define Bdim 32
#define Sdim 2048
#define Ddim 1024
#define Udim 1024
#define BS   (Bdim * Sdim)   // 65536 rows of the big GEMM

// ---- device scratch (no cudaMalloc allowed) ----
__device__ float g_dec_p[Bdim * Udim];            // [B,U]
__device__ float g_scores[Bdim * Sdim];           // [B,S]
__device__ float g_wpart[8 * Bdim * Ddim];        // s-split partials of attn-weighted h_enc
__device__ __half g_Ahi[(size_t)BS * Ddim];       // h_enc fp16 hi (128MB)
__device__ __half g_Bhi[(size_t)Udim * Ddim];     // W_enc^T fp16 hi [u][d]
__device__ __half g_Blo[(size_t)Udim * Ddim];     // W_enc^T fp16 lo [u][d]

// ============================================================================
// PTX helpers (portable sm_80-level ISA: cp.async / ldmatrix / mma.sync)
// ============================================================================
__device__ __forceinline__ uint32_t smem_to_u32(const void* p) {
    uint32_t a;
    asm("{ .reg .u64 t; cvta.to.shared.u64 t, %1; cvt.u32.u64 %0, t; }" : "=r"(a) : "l"(p));
    return a;
}
#define CP_ASYNC16(dst, src) \
    asm volatile("cp.async.cg.shared.global [%0], [%1], 16;" :: "r"(dst), "l"(src) : "memory")
#define CP_COMMIT() asm volatile("cp.async.commit_group;" ::: "memory")
#define CP_WAIT1()  asm volatile("cp.async.wait_group 1;" ::: "memory")
#define CP_WAIT0()  asm volatile("cp.async.wait_group 0;" ::: "memory")

__device__ __forceinline__ void ldsm4(uint32_t* r, uint32_t addr) {
    asm volatile("ldmatrix.sync.aligned.m8n8.x4.shared.b16 {%0,%1,%2,%3}, [%4];"
                 : "=r"(r[0]), "=r"(r[1]), "=r"(r[2]), "=r"(r[3]) : "r"(addr));
}
// D(f32) += A(f16,4regs) * B(f16,2regs)   m16n8k16 row.col
__device__ __forceinline__ void mma_f16(float* d, const uint32_t* a, uint32_t b0, uint32_t b1) {
    asm volatile(
        "mma.sync.aligned.m16n8k16.row.col.f32.f16.f16.f32 "
        "{%0,%1,%2,%3}, {%4,%5,%6,%7}, {%8,%9}, {%0,%1,%2,%3};"
        : "+f"(d[0]), "+f"(d[1]), "+f"(d[2]), "+f"(d[3])
        : "r"(a[0]), "r"(a[1]), "r"(a[2]), "r"(a[3]), "r"(b0), "r"(b1));
}

// fast fp32 tanh (Eigen/XLA rational 13/6, ~1e-7 core error)
__device__ __forceinline__ float tanh_fast(float x) {
    float xc = fminf(fmaxf(x, -7.99f), 7.99f);
    float x2 = xc * xc;
    float p = -2.76076847742355e-16f;
    p = fmaf(p, x2, 2.00018790482477e-13f);
    p = fmaf(p, x2, -8.60467152213735e-11f);
    p = fmaf(p, x2, 5.12229709037114e-08f);
    p = fmaf(p, x2, 1.48572235717979e-05f);
    p = fmaf(p, x2, 6.37261928875436e-04f);
    p = fmaf(p, x2, 4.89352455891786e-03f);
    p = p * xc;
    float q = 1.19825839466702e-06f;
    q = fmaf(q, x2, 1.18534705686654e-04f);
    q = fmaf(q, x2, 2.26843463243900e-03f);
    q = fmaf(q, x2, 4.89352518554385e-03f);
    return __fdividef(p, q);
}

// ============================================================================
// Kernel 0a: convert h_enc -> fp16 hi (same layout)
// ============================================================================
__global__ __launch_bounds__(256) void conv_h_kernel(const float* __restrict__ src) {
    size_t i = ((size_t)blockIdx.x * 256 + threadIdx.x) * 4;
    float4 v = *reinterpret_cast<const float4*>(src + i);
    __half2 h01 = __floats2half2_rn(v.x, v.y);
    __half2 h23 = __floats2half2_rn(v.z, v.w);
    *reinterpret_cast<__half2*>(g_Ahi + i)     = h01;
    *reinterpret_cast<__half2*>(g_Ahi + i + 2) = h23;
}

// ============================================================================
// Kernel 0b: W_enc [D,U] -> transposed fp16 hi/lo [U,D]
// ============================================================================
__global__ __launch_bounds__(256) void conv_w_kernel(const float* __restrict__ W) {
    __shared__ float s[32][33];
    int tx = threadIdx.x, ty = threadIdx.y;     // 32 x 8
    int u0 = blockIdx.x * 32, d0 = blockIdx.y * 32;
    #pragma unroll
    for (int k = 0; k < 4; ++k)
        s[ty + k * 8][tx] = W[(size_t)(d0 + ty + k * 8) * Udim + u0 + tx];
    __syncthreads();
    #pragma unroll
    for (int k = 0; k < 4; ++k) {
        float v = s[tx][ty + k * 8];
        __half hi = __float2half_rn(v);
        __half lo = __float2half_rn(v - __half2float(hi));
        size_t o = (size_t)(u0 + ty + k * 8) * Ddim + d0 + tx;
        g_Bhi[o] = hi;
        g_Blo[o] = lo;
    }
}

// ============================================================================
// Kernel 1: dec_p[b,u] = b_dec[u] + sum_d h_dec[b,d] * W_dec[d,u]
// ============================================================================
__global__ __launch_bounds__(256) void decp_kernel(const float* __restrict__ h_dec,
                                                   const float* __restrict__ W_dec,
                                                   const float* __restrict__ b_dec) {
    __shared__ float hv[Ddim];
    const int b = blockIdx.x;
    const int u = blockIdx.y * 256 + threadIdx.x;
    for (int d = threadIdx.x; d < Ddim; d += 256) hv[d] = h_dec[b * Ddim + d];
    __syncthreads();
    float acc = b_dec[u];
    #pragma unroll 8
    for (int d = 0; d < Ddim; ++d) acc = fmaf(hv[d], W_dec[d * Udim + u], acc);
    g_dec_p[b * Udim + u] = acc;
}

// ============================================================================
// Kernel 2: score GEMM via mma.sync fp16 (A=hi, B=hi+lo -> 2 products) with
// fused tanh/W_com epilogue. CTA 128 rows; 8 n-groups of 128 cols; BK=32.
// Flat 256-iteration mainloop, 3-stage cp.async, ONE __syncthreads per iter.
// Smem rows padded to 80B -> conflict-free ldmatrix.
// ============================================================================
#define MAT_BYTES 10240u                // 128 rows * 80B per matrix
#define STG_BYTES 30720u                // A-hi + B-hi + B-lo
#define NSTG 3
#define OFF_DECW (NSTG * STG_BYTES)     // float2[1024] = 8192
#define OFF_RED  (OFF_DECW + 8192u)     // float[128][2] = 1024
#define SMEM_SCORE (OFF_RED + 1024u)

__device__ __forceinline__ void score_loads(int t, int tid, int row0, uint32_t sbase) {
    const int kt = t & 31, ng = t >> 5;
    const uint32_t stg = (uint32_t)(t % NSTG) * STG_BYTES;
    // A-hi: 128 rows x 32 k x 2B = 8KB = 512 x 16B
    #pragma unroll
    for (int k = 0; k < 2; ++k) {
        int idx = tid + k * 256;
        int r = idx >> 2, seg = idx & 3;
        const __half* src = g_Ahi + (((size_t)(row0 + r)) << 10) + (kt << 5) + (seg << 3);
        uint32_t dst = sbase + stg + (uint32_t)(r * 80 + seg * 16);
        CP_ASYNC16(dst, src);
    }
    // B hi+lo: 2 x 8KB
    const int u0 = ng * 128;
    #pragma unroll
    for (int k = 0; k < 4; ++k) {
        int idx = tid + k * 256;
        int h = idx >> 9, r = (idx >> 2) & 127, seg = idx & 3;
        const __half* src =
            (h ? g_Blo : g_Bhi) + (((size_t)(u0 + r)) << 10) + (kt << 5) + (seg << 3);
        uint32_t dst = sbase + stg + MAT_BYTES + (uint32_t)h * MAT_BYTES +
                       (uint32_t)(r * 80 + seg * 16);
        CP_ASYNC16(dst, src);
    }
}

__global__ __launch_bounds__(256, 2) void score_mma_kernel(const float* __restrict__ W_com,
                                                           const float* __restrict__ b_com,
                                                           const float* __restrict__ b_enc) {
    extern __shared__ char sm[];
    const uint32_t sbase = smem_to_u32(sm);
    float2* decw = reinterpret_cast<float2*>(sm + OFF_DECW);
    float* red   = reinterpret_cast<float*>(sm + OFF_RED);

    const int tid  = threadIdx.x;
    const int wid  = tid >> 5, lane = tid & 31;
    const int wm   = wid >> 1;          // 0..3 -> rows wm*32
    const int wn   = wid & 1;           // 0..1 -> cols wn*64
    const int row0 = blockIdx.x * 128;
    const int b    = row0 >> 11;

    // prefetch t=0,1 while decw fills
    score_loads(0, tid, row0, sbase);
    CP_COMMIT();
    score_loads(1, tid, row0, sbase);
    CP_COMMIT();

    for (int i = tid; i < Udim; i += 256)
        decw[i] = make_float2(g_dec_p[b * Udim + i] + b_enc[i], W_com[i]);

    float rs[4] = {0.f, 0.f, 0.f, 0.f};
    float acc[2][8][4];
    const uint32_t lrow = (uint32_t)(lane & 15) * 80u + ((uint32_t)(lane >> 4) << 4);

    #pragma unroll 1
    for (int t = 0; t < 256; ++t) {
        const int kt = t & 31;
        if (kt == 0) {
            #pragma unroll
            for (int mi = 0; mi < 2; ++mi)
                #pragma unroll
                for (int nj = 0; nj < 8; ++nj)
                    #pragma unroll
                    for (int e = 0; e < 4; ++e) acc[mi][nj][e] = 0.f;
        }
        if (t == 255) { CP_WAIT0(); } else { CP_WAIT1(); }
        __syncthreads();
        if (t + 2 < 256) {
            score_loads(t + 2, tid, row0, sbase);
            CP_COMMIT();
        }

        const uint32_t sA  = sbase + (uint32_t)(t % NSTG) * STG_BYTES;
        const uint32_t sBh = sA + MAT_BYTES;
        #pragma unroll
        for (int ks = 0; ks < 2; ++ks) {
            uint32_t ah[2][4];
            uint32_t aaddr = sA + (uint32_t)(wm * 32) * 80u + lrow + (uint32_t)ks * 32u;
            ldsm4(ah[0], aaddr);
            ldsm4(ah[1], aaddr + 16u * 80u);
            #pragma unroll
            for (int p = 0; p < 4; ++p) {
                uint32_t baddr = sBh + (uint32_t)(wn * 64 + p * 16) * 80u + lrow +
                                 (uint32_t)ks * 32u;
                uint32_t bh[4], bl[4];
                ldsm4(bh, baddr);
                ldsm4(bl, baddr + MAT_BYTES);
                mma_f16(acc[0][2 * p],     ah[0], bh[0], bh[2]);
                mma_f16(acc[0][2 * p + 1], ah[0], bh[1], bh[3]);
                mma_f16(acc[1][2 * p],     ah[1], bh[0], bh[2]);
                mma_f16(acc[1][2 * p + 1], ah[1], bh[1], bh[3]);
                mma_f16(acc[0][2 * p],     ah[0], bl[0], bl[2]);
                mma_f16(acc[0][2 * p + 1], ah[0], bl[1], bl[3]);
                mma_f16(acc[1][2 * p],     ah[1], bl[0], bl[2]);
                mma_f16(acc[1][2 * p + 1], ah[1], bl[1], bl[3]);
            }
        }

        if (kt == 31) {
            // epilogue: x = enc_p + (dec_p + b_enc); rs += W_com * tanh(x)
            const int ng = t >> 5;
            #pragma unroll
            for (int mi = 0; mi < 2; ++mi) {
                #pragma unroll
                for (int nj = 0; nj < 8; ++nj) {
                    int u = ng * 128 + wn * 64 + nj * 8 + 2 * (lane & 3);
                    float2 w0 = decw[u];
                    float2 w1 = decw[u + 1];
                    rs[2 * mi] += w0.y * tanh_fast(acc[mi][nj][0] + w0.x) +
                                  w1.y * tanh_fast(acc[mi][nj][1] + w1.x);
                    rs[2 * mi + 1] += w0.y * tanh_fast(acc[mi][nj][2] + w0.x) +
                                      w1.y * tanh_fast(acc[mi][nj][3] + w1.x);
                }
            }
        }
    }

    // reduce the 4-lane quads that share a row
    #pragma unroll
    for (int i = 0; i < 4; ++i) {
        rs[i] += __shfl_xor_sync(0xffffffffu, rs[i], 1);
        rs[i] += __shfl_xor_sync(0xffffffffu, rs[i], 2);
    }
    if ((lane & 3) == 0) {
        #pragma unroll
        for (int mi = 0; mi < 2; ++mi)
            #pragma unroll
            for (int h = 0; h < 2; ++h) {
                int row = wm * 32 + mi * 16 + h * 8 + (lane >> 2);
                red[row * 2 + wn] = rs[2 * mi + h];
            }
    }
    __syncthreads();
    if (tid < 128)
        g_scores[row0 + tid] = red[tid * 2] + red[tid * 2 + 1] + __ldg(&b_com[0]);
}

// ============================================================================
// Kernel 3: softmax over S per batch
// ============================================================================
__global__ __launch_bounds__(256) void softmax_kernel(float* __restrict__ attn_out) {
    __shared__ float sm[256];
    const int b = blockIdx.x;
    const int tid = threadIdx.x;
    float v[8];
    float mx = -3.4e38f;
    #pragma unroll
    for (int i = 0; i < 8; ++i) {
        v[i] = g_scores[b * Sdim + tid + i * 256];
        mx = fmaxf(mx, v[i]);
    }
    sm[tid] = mx;
    __syncthreads();
    for (int off = 128; off > 0; off >>= 1) {
        if (tid < off) sm[tid] = fmaxf(sm[tid], sm[tid + off]);
        __syncthreads();
    }
    const float m = sm[0];
    __syncthreads();
    float sum = 0.f;
    #pragma unroll
    for (int i = 0; i < 8; ++i) {
        v[i] = expf(v[i] - m);
        sum += v[i];
    }
    sm[tid] = sum;
    __syncthreads();
    for (int off = 128; off > 0; off >>= 1) {
        if (tid < off) sm[tid] += sm[tid + off];
        __syncthreads();
    }
    const float inv = 1.f / sm[0];
    #pragma unroll
    for (int i = 0; i < 8; ++i) attn_out[b * Sdim + tid + i * 256] = v[i] * inv;
}

// ============================================================================
// Kernel 4: weighted[b,d] = sum_s attn[b,s] * h_enc[b,s,d]  (8 s-splits)
// ============================================================================
__global__ __launch_bounds__(256) void weighted_kernel(const float* __restrict__ h_enc,
                                                       const float* __restrict__ attn) {
    const int b = blockIdx.x;
    const int d = blockIdx.y * 256 + threadIdx.x;
    const int spl = blockIdx.z;
    const int s0 = spl * (Sdim / 8);
    const float* base = h_enc + ((size_t)b * Sdim + s0) * Ddim + d;
    const float* av = attn + b * Sdim + s0;
    float acc = 0.f;
    #pragma unroll 8
    for (int s = 0; s < Sdim / 8; ++s) acc = fmaf(__ldg(av + s), base[(size_t)s * Ddim], acc);
    g_wpart[(spl * Bdim + b) * Ddim + d] = acc;
}

// ============================================================================
// Kernel 5: context[b,u] = b_enc[u] + sum_d weighted[b,d] * W_enc[d,u]
// ============================================================================
__global__ __launch_bounds__(256) void context_kernel(const float* __restrict__ W_enc,
                                                      const float* __restrict__ b_enc,
                                                      float* __restrict__ out_ctx) {
    __shared__ float wv[Ddim];
    const int b = blockIdx.x;
    const int u = blockIdx.y * 256 + threadIdx.x;
    for (int d = threadIdx.x; d < Ddim; d += 256) {
        float s = 0.f;
        #pragma unroll
        for (int p = 0; p < 8; ++p) s += g_wpart[(p * Bdim + b) * Ddim + d];
        wv[d] = s;
    }
    __syncthreads();
    float acc = b_enc[u];
    #pragma unroll 8
    for (int d = 0; d < Ddim; ++d) acc = fmaf(wv[d], W_enc[d * Udim + u], acc);
    out_ctx[b * Udim + u] = acc;
}

// ============================================================================
extern "C" void kernel_launch(void* const* d_in, const int* in_sizes, int n_in,
                              void* d_out, int out_size) {
    const float* h_enc = (const float*)d_in[0];
    const float* h_dec = (const float*)d_in[1];
    const float* W_enc = (const float*)d_in[2];
    const float* b_enc = (const float*)d_in[3];
    const float* W_dec = (const float*)d_in[4];
    const float* b_dec = (const float*)d_in[5];
    const float* W_com = (const float*)d_in[6];
    const float* b_com = (const float*)d_in[7];

    float* out = (float*)d_out;
    float* out_ctx = out;                 // [B,U]
    float* out_attn = out + Bdim * Udim;  // [B,S,1]

    cudaFuncSetAttribute(score_mma_kernel, cudaFuncAttributeMaxDynamicSharedMemorySize,
                         SMEM_SCORE);

    conv_h_kernel<<<(BS * Ddim) / (256 * 4), 256>>>(h_enc);
    conv_w_kernel<<<dim3(Udim / 32, Ddim / 32), dim3(32, 8)>>>(W_enc);
    decp_kernel<<<dim3(Bdim, Udim / 256), 256>>>(h_dec, W_dec, b_dec);
    score_mma_kernel<<<BS / 128, 256, SMEM_SCORE>>>(W_com, b_com, b_enc);
    softmax_kernel<<<Bdim, 256>>>(out_attn);
    weighted_kernel<<<dim3(Bdim, Ddim / 256, 8), 256>>>(h_enc, out_attn);
    context_kernel<<<dim3(Bdim, Udim / 256), 256>>>(W_enc, b_enc, out_ctx);
}

// round 11
// speedup vs baseline: 4.0955x; 1.4007x over previous
#include <cuda_runtime.h>
#include <cuda_fp16.h>
#include <math.h>
#include <stdint.h>

// Problem dims (fixed per reference)
#define Bdim 32
#define Sdim 2048
#define Ddim 1024
#define Udim 1024
#define BS   (Bdim * Sdim)   // 65536 rows of the big GEMM

// ---- device scratch (no cudaMalloc allowed) ----
__device__ float g_dec_p[Bdim * Udim];            // [B,U]
__device__ float g_scores[Bdim * Sdim];           // [B,S]
__device__ float g_wpart[8 * Bdim * Ddim];        // s-split partials of attn-weighted h_enc
__device__ __half g_Ahi[(size_t)BS * Ddim];       // h_enc fp16 (128MB)
__device__ __half g_Bhi[(size_t)Udim * Ddim];     // W_enc^T fp16 [u][d]

// ============================================================================
// PTX helpers (portable sm_80-level ISA: cp.async / ldmatrix / mma.sync)
// ============================================================================
__device__ __forceinline__ uint32_t smem_to_u32(const void* p) {
    uint32_t a;
    asm("{ .reg .u64 t; cvta.to.shared.u64 t, %1; cvt.u32.u64 %0, t; }" : "=r"(a) : "l"(p));
    return a;
}
#define CP_ASYNC16(dst, src) \
    asm volatile("cp.async.cg.shared.global [%0], [%1], 16;" :: "r"(dst), "l"(src) : "memory")
#define CP_COMMIT() asm volatile("cp.async.commit_group;" ::: "memory")
#define CP_WAIT2()  asm volatile("cp.async.wait_group 2;" ::: "memory")
#define CP_WAIT1()  asm volatile("cp.async.wait_group 1;" ::: "memory")
#define CP_WAIT0()  asm volatile("cp.async.wait_group 0;" ::: "memory")

__device__ __forceinline__ void ldsm4(uint32_t* r, uint32_t addr) {
    asm volatile("ldmatrix.sync.aligned.m8n8.x4.shared.b16 {%0,%1,%2,%3}, [%4];"
                 : "=r"(r[0]), "=r"(r[1]), "=r"(r[2]), "=r"(r[3]) : "r"(addr));
}
// D(f32) += A(f16,4regs) * B(f16,2regs)   m16n8k16 row.col
__device__ __forceinline__ void mma_f16(float* d, const uint32_t* a, uint32_t b0, uint32_t b1) {
    asm volatile(
        "mma.sync.aligned.m16n8k16.row.col.f32.f16.f16.f32 "
        "{%0,%1,%2,%3}, {%4,%5,%6,%7}, {%8,%9}, {%0,%1,%2,%3};"
        : "+f"(d[0]), "+f"(d[1]), "+f"(d[2]), "+f"(d[3])
        : "r"(a[0]), "r"(a[1]), "r"(a[2]), "r"(a[3]), "r"(b0), "r"(b1));
}

// fast fp32 tanh (Eigen/XLA rational 13/6, ~1e-7 core error)
__device__ __forceinline__ float tanh_fast(float x) {
    float xc = fminf(fmaxf(x, -7.99f), 7.99f);
    float x2 = xc * xc;
    float p = -2.76076847742355e-16f;
    p = fmaf(p, x2, 2.00018790482477e-13f);
    p = fmaf(p, x2, -8.60467152213735e-11f);
    p = fmaf(p, x2, 5.12229709037114e-08f);
    p = fmaf(p, x2, 1.48572235717979e-05f);
    p = fmaf(p, x2, 6.37261928875436e-04f);
    p = fmaf(p, x2, 4.89352455891786e-03f);
    p = p * xc;
    float q = 1.19825839466702e-06f;
    q = fmaf(q, x2, 1.18534705686654e-04f);
    q = fmaf(q, x2, 2.26843463243900e-03f);
    q = fmaf(q, x2, 4.89352518554385e-03f);
    return __fdividef(p, q);
}

// ============================================================================
// Kernel 0a: convert h_enc -> fp16 (same layout)
// ============================================================================
__global__ __launch_bounds__(256) void conv_h_kernel(const float* __restrict__ src) {
    size_t i = ((size_t)blockIdx.x * 256 + threadIdx.x) * 4;
    float4 v = *reinterpret_cast<const float4*>(src + i);
    *reinterpret_cast<__half2*>(g_Ahi + i)     = __floats2half2_rn(v.x, v.y);
    *reinterpret_cast<__half2*>(g_Ahi + i + 2) = __floats2half2_rn(v.z, v.w);
}

// ============================================================================
// Kernel 0b: W_enc [D,U] -> transposed fp16 [U,D]
// ============================================================================
__global__ __launch_bounds__(256) void conv_w_kernel(const float* __restrict__ W) {
    __shared__ float s[32][33];
    int tx = threadIdx.x, ty = threadIdx.y;     // 32 x 8
    int u0 = blockIdx.x * 32, d0 = blockIdx.y * 32;
    #pragma unroll
    for (int k = 0; k < 4; ++k)
        s[ty + k * 8][tx] = W[(size_t)(d0 + ty + k * 8) * Udim + u0 + tx];
    __syncthreads();
    #pragma unroll
    for (int k = 0; k < 4; ++k) {
        float v = s[tx][ty + k * 8];
        g_Bhi[(size_t)(u0 + ty + k * 8) * Ddim + d0 + tx] = __float2half_rn(v);
    }
}

// ============================================================================
// Kernel 1: dec_p[b,u] = b_dec[u] + sum_d h_dec[b,d] * W_dec[d,u]
// ============================================================================
__global__ __launch_bounds__(256) void decp_kernel(const float* __restrict__ h_dec,
                                                   const float* __restrict__ W_dec,
                                                   const float* __restrict__ b_dec) {
    __shared__ float hv[Ddim];
    const int b = blockIdx.x;
    const int u = blockIdx.y * 256 + threadIdx.x;
    for (int d = threadIdx.x; d < Ddim; d += 256) hv[d] = h_dec[b * Ddim + d];
    __syncthreads();
    float acc = b_dec[u];
    #pragma unroll 8
    for (int d = 0; d < Ddim; ++d) acc = fmaf(hv[d], W_dec[d * Udim + u], acc);
    g_dec_p[b * Udim + u] = acc;
}

// ============================================================================
// Kernel 2: score GEMM via mma.sync fp16 (single product) + fused epilogue.
// CTA 128 rows; 8 n-groups of 128 cols; BK=32. Flat 256-iter mainloop,
// 4-stage cp.async (3-deep prefetch), ONE __syncthreads per iter.
// Smem rows padded to 80B -> conflict-free ldmatrix.
// ============================================================================
#define MAT_BYTES 10240u                // 128 rows * 80B per matrix
#define STG_BYTES 20480u                // A + B
#define NSTG 4
#define OFF_DECW (NSTG * STG_BYTES)     // float2[1024] = 8192
#define OFF_RED  (OFF_DECW + 8192u)     // float[128][2] = 1024
#define SMEM_SCORE (OFF_RED + 1024u)

__device__ __forceinline__ void score_loads(int t, int tid, int row0, uint32_t sbase) {
    const int kt = t & 31, ng = t >> 5;
    const uint32_t stg = (uint32_t)(t & (NSTG - 1)) * STG_BYTES;
    // A: 128 rows x 32 k x 2B = 8KB = 512 x 16B
    #pragma unroll
    for (int k = 0; k < 2; ++k) {
        int idx = tid + k * 256;
        int r = idx >> 2, seg = idx & 3;
        const __half* src = g_Ahi + (((size_t)(row0 + r)) << 10) + (kt << 5) + (seg << 3);
        uint32_t dst = sbase + stg + (uint32_t)(r * 80 + seg * 16);
        CP_ASYNC16(dst, src);
    }
    // B: 8KB
    const int u0 = ng * 128;
    #pragma unroll
    for (int k = 0; k < 2; ++k) {
        int idx = tid + k * 256;
        int r = idx >> 2, seg = idx & 3;
        const __half* src = g_Bhi + (((size_t)(u0 + r)) << 10) + (kt << 5) + (seg << 3);
        uint32_t dst = sbase + stg + MAT_BYTES + (uint32_t)(r * 80 + seg * 16);
        CP_ASYNC16(dst, src);
    }
}

__global__ __launch_bounds__(256, 2) void score_mma_kernel(const float* __restrict__ W_com,
                                                           const float* __restrict__ b_com,
                                                           const float* __restrict__ b_enc) {
    extern __shared__ char sm[];
    const uint32_t sbase = smem_to_u32(sm);
    float2* decw = reinterpret_cast<float2*>(sm + OFF_DECW);
    float* red   = reinterpret_cast<float*>(sm + OFF_RED);

    const int tid  = threadIdx.x;
    const int wid  = tid >> 5, lane = tid & 31;
    const int wm   = wid >> 1;          // 0..3 -> rows wm*32
    const int wn   = wid & 1;           // 0..1 -> cols wn*64
    const int row0 = blockIdx.x * 128;
    const int b    = row0 >> 11;

    // 3-deep prefetch while decw fills
    score_loads(0, tid, row0, sbase);
    CP_COMMIT();
    score_loads(1, tid, row0, sbase);
    CP_COMMIT();
    score_loads(2, tid, row0, sbase);
    CP_COMMIT();

    for (int i = tid; i < Udim; i += 256)
        decw[i] = make_float2(g_dec_p[b * Udim + i] + b_enc[i], W_com[i]);

    float rs[4] = {0.f, 0.f, 0.f, 0.f};
    float acc[2][8][4];
    const uint32_t lrow = (uint32_t)(lane & 15) * 80u + ((uint32_t)(lane >> 4) << 4);

    #pragma unroll 1
    for (int t = 0; t < 256; ++t) {
        const int kt = t & 31;
        if (kt == 0) {
            #pragma unroll
            for (int mi = 0; mi < 2; ++mi)
                #pragma unroll
                for (int nj = 0; nj < 8; ++nj)
                    #pragma unroll
                    for (int e = 0; e < 4; ++e) acc[mi][nj][e] = 0.f;
        }
        if (t < 254) { CP_WAIT2(); } else if (t == 254) { CP_WAIT1(); } else { CP_WAIT0(); }
        __syncthreads();
        if (t + 3 < 256) {
            score_loads(t + 3, tid, row0, sbase);
            CP_COMMIT();
        }

        const uint32_t sA = sbase + (uint32_t)(t & (NSTG - 1)) * STG_BYTES;
        const uint32_t sB = sA + MAT_BYTES;
        #pragma unroll
        for (int ks = 0; ks < 2; ++ks) {
            uint32_t ah[2][4];
            uint32_t aaddr = sA + (uint32_t)(wm * 32) * 80u + lrow + (uint32_t)ks * 32u;
            ldsm4(ah[0], aaddr);
            ldsm4(ah[1], aaddr + 16u * 80u);
            #pragma unroll
            for (int p = 0; p < 4; ++p) {
                uint32_t baddr = sB + (uint32_t)(wn * 64 + p * 16) * 80u + lrow +
                                 (uint32_t)ks * 32u;
                uint32_t bh[4];
                ldsm4(bh, baddr);
                mma_f16(acc[0][2 * p],     ah[0], bh[0], bh[2]);
                mma_f16(acc[0][2 * p + 1], ah[0], bh[1], bh[3]);
                mma_f16(acc[1][2 * p],     ah[1], bh[0], bh[2]);
                mma_f16(acc[1][2 * p + 1], ah[1], bh[1], bh[3]);
            }
        }

        if (kt == 31) {
            // epilogue: x = enc_p + (dec_p + b_enc); rs += W_com * tanh(x)
            const int ng = t >> 5;
            #pragma unroll
            for (int mi = 0; mi < 2; ++mi) {
                #pragma unroll
                for (int nj = 0; nj < 8; ++nj) {
                    int u = ng * 128 + wn * 64 + nj * 8 + 2 * (lane & 3);
                    float2 w0 = decw[u];
                    float2 w1 = decw[u + 1];
                    rs[2 * mi] += w0.y * tanh_fast(acc[mi][nj][0] + w0.x) +
                                  w1.y * tanh_fast(acc[mi][nj][1] + w1.x);
                    rs[2 * mi + 1] += w0.y * tanh_fast(acc[mi][nj][2] + w0.x) +
                                      w1.y * tanh_fast(acc[mi][nj][3] + w1.x);
                }
            }
        }
    }

    // reduce the 4-lane quads that share a row
    #pragma unroll
    for (int i = 0; i < 4; ++i) {
        rs[i] += __shfl_xor_sync(0xffffffffu, rs[i], 1);
        rs[i] += __shfl_xor_sync(0xffffffffu, rs[i], 2);
    }
    if ((lane & 3) == 0) {
        #pragma unroll
        for (int mi = 0; mi < 2; ++mi)
            #pragma unroll
            for (int h = 0; h < 2; ++h) {
                int row = wm * 32 + mi * 16 + h * 8 + (lane >> 2);
                red[row * 2 + wn] = rs[2 * mi + h];
            }
    }
    __syncthreads();
    if (tid < 128)
        g_scores[row0 + tid] = red[tid * 2] + red[tid * 2 + 1] + __ldg(&b_com[0]);
}

// ============================================================================
// Kernel 3: softmax over S per batch
// ============================================================================
__global__ __launch_bounds__(256) void softmax_kernel(float* __restrict__ attn_out) {
    __shared__ float sm[256];
    const int b = blockIdx.x;
    const int tid = threadIdx.x;
    float v[8];
    float mx = -3.4e38f;
    #pragma unroll
    for (int i = 0; i < 8; ++i) {
        v[i] = g_scores[b * Sdim + tid + i * 256];
        mx = fmaxf(mx, v[i]);
    }
    sm[tid] = mx;
    __syncthreads();
    for (int off = 128; off > 0; off >>= 1) {
        if (tid < off) sm[tid] = fmaxf(sm[tid], sm[tid + off]);
        __syncthreads();
    }
    const float m = sm[0];
    __syncthreads();
    float sum = 0.f;
    #pragma unroll
    for (int i = 0; i < 8; ++i) {
        v[i] = expf(v[i] - m);
        sum += v[i];
    }
    sm[tid] = sum;
    __syncthreads();
    for (int off = 128; off > 0; off >>= 1) {
        if (tid < off) sm[tid] += sm[tid + off];
        __syncthreads();
    }
    const float inv = 1.f / sm[0];
    #pragma unroll
    for (int i = 0; i < 8; ++i) attn_out[b * Sdim + tid + i * 256] = v[i] * inv;
}

// ============================================================================
// Kernel 4: weighted[b,d4] = sum_s attn[b,s] * h_enc[b,s,d4]  (8 s-splits,
// float4 per thread for MLP)
// ============================================================================
__global__ __launch_bounds__(256) void weighted_kernel(const float* __restrict__ h_enc,
                                                       const float* __restrict__ attn) {
    const int b = blockIdx.x;
    const int d4 = threadIdx.x;          // 256 threads x 4 floats = 1024
    const int spl = blockIdx.y;
    const int s0 = spl * (Sdim / 8);
    const float4* base =
        reinterpret_cast<const float4*>(h_enc + ((size_t)b * Sdim + s0) * Ddim) + d4;
    const float* av = attn + b * Sdim + s0;
    float4 acc = make_float4(0.f, 0.f, 0.f, 0.f);
    #pragma unroll 4
    for (int s = 0; s < Sdim / 8; ++s) {
        float a = __ldg(av + s);
        float4 v = base[(size_t)s * (Ddim / 4)];
        acc.x = fmaf(a, v.x, acc.x);
        acc.y = fmaf(a, v.y, acc.y);
        acc.z = fmaf(a, v.z, acc.z);
        acc.w = fmaf(a, v.w, acc.w);
    }
    *reinterpret_cast<float4*>(g_wpart + (size_t)(spl * Bdim + b) * Ddim + d4 * 4) = acc;
}

// ============================================================================
// Kernel 5: context[b,u] = b_enc[u] + sum_d weighted[b,d] * W_enc[d,u]
// ============================================================================
__global__ __launch_bounds__(256) void context_kernel(const float* __restrict__ W_enc,
                                                      const float* __restrict__ b_enc,
                                                      float* __restrict__ out_ctx) {
    __shared__ float wv[Ddim];
    const int b = blockIdx.x;
    const int u = blockIdx.y * 256 + threadIdx.x;
    for (int d = threadIdx.x; d < Ddim; d += 256) {
        float s = 0.f;
        #pragma unroll
        for (int p = 0; p < 8; ++p) s += g_wpart[(p * Bdim + b) * Ddim + d];
        wv[d] = s;
    }
    __syncthreads();
    float acc = b_enc[u];
    #pragma unroll 8
    for (int d = 0; d < Ddim; ++d) acc = fmaf(wv[d], W_enc[d * Udim + u], acc);
    out_ctx[b * Udim + u] = acc;
}

// ============================================================================
extern "C" void kernel_launch(void* const* d_in, const int* in_sizes, int n_in,
                              void* d_out, int out_size) {
    const float* h_enc = (const float*)d_in[0];
    const float* h_dec = (const float*)d_in[1];
    const float* W_enc = (const float*)d_in[2];
    const float* b_enc = (const float*)d_in[3];
    const float* W_dec = (const float*)d_in[4];
    const float* b_dec = (const float*)d_in[5];
    const float* W_com = (const float*)d_in[6];
    const float* b_com = (const float*)d_in[7];

    float* out = (float*)d_out;
    float* out_ctx = out;                 // [B,U]
    float* out_attn = out + Bdim * Udim;  // [B,S,1]

    cudaFuncSetAttribute(score_mma_kernel, cudaFuncAttributeMaxDynamicSharedMemorySize,
                         SMEM_SCORE);

    conv_h_kernel<<<(BS * Ddim) / (256 * 4), 256>>>(h_enc);
    conv_w_kernel<<<dim3(Udim / 32, Ddim / 32), dim3(32, 8)>>>(W_enc);
    decp_kernel<<<dim3(Bdim, Udim / 256), 256>>>(h_dec, W_dec, b_dec);
    score_mma_kernel<<<BS / 128, 256, SMEM_SCORE>>>(W_com, b_com, b_enc);
    softmax_kernel<<<Bdim, 256>>>(out_attn);
    weighted_kernel<<<dim3(Bdim, 8), 256>>>(h_enc, out_attn);
    context_kernel<<<dim3(Bdim, Udim / 256), 256>>>(W_enc, b_enc, out_ctx);
}

// round 12
// speedup vs baseline: 4.1531x; 1.0141x over previous
#include <cuda_runtime.h>
#include <cuda_fp16.h>
#include <math.h>
#include <stdint.h>

// Problem dims (fixed per reference)
#define Bdim 32
#define Sdim 2048
#define Ddim 1024
#define Udim 1024
#define BS   (Bdim * Sdim)   // 65536 rows of the big GEMM

// ---- device scratch (no cudaMalloc allowed) ----
__device__ float g_dec_p[Bdim * Udim];            // [B,U]
__device__ float g_scores[Bdim * Sdim];           // [B,S]
__device__ float g_wpart[8 * Bdim * Ddim];        // s-split partials of attn-weighted h_enc
__device__ __half g_Ahi[(size_t)BS * Ddim];       // h_enc fp16 (128MB)
__device__ __half g_Bhi[(size_t)Udim * Ddim];     // W_enc^T fp16 [u][d]

// ============================================================================
// PTX helpers (portable sm_80-level ISA: cp.async / ldmatrix / mma.sync)
// ============================================================================
__device__ __forceinline__ uint32_t smem_to_u32(const void* p) {
    uint32_t a;
    asm("{ .reg .u64 t; cvta.to.shared.u64 t, %1; cvt.u32.u64 %0, t; }" : "=r"(a) : "l"(p));
    return a;
}
#define CP_ASYNC16(dst, src) \
    asm volatile("cp.async.cg.shared.global [%0], [%1], 16;" :: "r"(dst), "l"(src) : "memory")
#define CP_COMMIT() asm volatile("cp.async.commit_group;" ::: "memory")
#define CP_WAIT2()  asm volatile("cp.async.wait_group 2;" ::: "memory")
#define CP_WAIT1()  asm volatile("cp.async.wait_group 1;" ::: "memory")
#define CP_WAIT0()  asm volatile("cp.async.wait_group 0;" ::: "memory")

__device__ __forceinline__ void ldsm4(uint32_t* r, uint32_t addr) {
    asm volatile("ldmatrix.sync.aligned.m8n8.x4.shared.b16 {%0,%1,%2,%3}, [%4];"
                 : "=r"(r[0]), "=r"(r[1]), "=r"(r[2]), "=r"(r[3]) : "r"(addr));
}
// D(f32) += A(f16,4regs) * B(f16,2regs)   m16n8k16 row.col
__device__ __forceinline__ void mma_f16(float* d, const uint32_t* a, uint32_t b0, uint32_t b1) {
    asm volatile(
        "mma.sync.aligned.m16n8k16.row.col.f32.f16.f16.f32 "
        "{%0,%1,%2,%3}, {%4,%5,%6,%7}, {%8,%9}, {%0,%1,%2,%3};"
        : "+f"(d[0]), "+f"(d[1]), "+f"(d[2]), "+f"(d[3])
        : "r"(a[0]), "r"(a[1]), "r"(a[2]), "r"(a[3]), "r"(b0), "r"(b1));
}

// fast fp32 tanh (Eigen/XLA rational 13/6, ~1e-7 core error)
__device__ __forceinline__ float tanh_fast(float x) {
    float xc = fminf(fmaxf(x, -7.99f), 7.99f);
    float x2 = xc * xc;
    float p = -2.76076847742355e-16f;
    p = fmaf(p, x2, 2.00018790482477e-13f);
    p = fmaf(p, x2, -8.60467152213735e-11f);
    p = fmaf(p, x2, 5.12229709037114e-08f);
    p = fmaf(p, x2, 1.48572235717979e-05f);
    p = fmaf(p, x2, 6.37261928875436e-04f);
    p = fmaf(p, x2, 4.89352455891786e-03f);
    p = p * xc;
    float q = 1.19825839466702e-06f;
    q = fmaf(q, x2, 1.18534705686654e-04f);
    q = fmaf(q, x2, 2.26843463243900e-03f);
    q = fmaf(q, x2, 4.89352518554385e-03f);
    return __fdividef(p, q);
}

// ============================================================================
// Kernel 0a: convert h_enc -> fp16 (same layout)
// ============================================================================
__global__ __launch_bounds__(256) void conv_h_kernel(const float* __restrict__ src) {
    size_t i = ((size_t)blockIdx.x * 256 + threadIdx.x) * 4;
    float4 v = *reinterpret_cast<const float4*>(src + i);
    *reinterpret_cast<__half2*>(g_Ahi + i)     = __floats2half2_rn(v.x, v.y);
    *reinterpret_cast<__half2*>(g_Ahi + i + 2) = __floats2half2_rn(v.z, v.w);
}

// ============================================================================
// Kernel 0b: W_enc [D,U] -> transposed fp16 [U,D]
// ============================================================================
__global__ __launch_bounds__(256) void conv_w_kernel(const float* __restrict__ W) {
    __shared__ float s[32][33];
    int tx = threadIdx.x, ty = threadIdx.y;     // 32 x 8
    int u0 = blockIdx.x * 32, d0 = blockIdx.y * 32;
    #pragma unroll
    for (int k = 0; k < 4; ++k)
        s[ty + k * 8][tx] = W[(size_t)(d0 + ty + k * 8) * Udim + u0 + tx];
    __syncthreads();
    #pragma unroll
    for (int k = 0; k < 4; ++k) {
        float v = s[tx][ty + k * 8];
        g_Bhi[(size_t)(u0 + ty + k * 8) * Ddim + d0 + tx] = __float2half_rn(v);
    }
}

// ============================================================================
// Kernel 1: dec_p[b,u] = b_dec[u] + sum_d h_dec[b,d] * W_dec[d,u]
// ============================================================================
__global__ __launch_bounds__(256) void decp_kernel(const float* __restrict__ h_dec,
                                                   const float* __restrict__ W_dec,
                                                   const float* __restrict__ b_dec) {
    __shared__ float hv[Ddim];
    const int b = blockIdx.x;
    const int u = blockIdx.y * 256 + threadIdx.x;
    for (int d = threadIdx.x; d < Ddim; d += 256) hv[d] = h_dec[b * Ddim + d];
    __syncthreads();
    float acc = b_dec[u];
    #pragma unroll 8
    for (int d = 0; d < Ddim; ++d) acc = fmaf(hv[d], W_dec[d * Udim + u], acc);
    g_dec_p[b * Udim + u] = acc;
}

// ============================================================================
// Kernel 2: score GEMM via mma.sync fp16 + fused tanh/W_com epilogue.
// CTA tile 128 x 256 (4 n-groups over U). 8 warps of 64x64 (wm=wid&1, wn=wid>>1).
// BK=32. Flat 128-iter mainloop, 4-stage cp.async (3-deep), ONE barrier/iter.
// Smem rows padded to 80B -> conflict-free ldmatrix.
// ============================================================================
#define A_BYTES  10240u                 // 128 rows * 80B
#define B_BYTES  20480u                 // 256 rows * 80B
#define STG_BYTES (A_BYTES + B_BYTES)   // 30720
#define NSTG 4
#define OFF_DECW (NSTG * STG_BYTES)     // 122880: float2[1024] = 8192
#define OFF_RED  (OFF_DECW + 8192u)     // float[128][4] = 2048
#define SMEM_SCORE (OFF_RED + 2048u)    // 133120

__device__ __forceinline__ void score_loads(int t, int tid, int row0, uint32_t sbase) {
    const int kt = t & 31, ng = t >> 5;
    const uint32_t stg = sbase + (uint32_t)(t & (NSTG - 1)) * STG_BYTES;
    // A: 128 rows x 32 k x 2B = 8KB = 512 x 16B  (2 per thread)
    #pragma unroll
    for (int k = 0; k < 2; ++k) {
        int idx = tid + k * 256;
        int r = idx >> 2, seg = idx & 3;
        const __half* src = g_Ahi + (((size_t)(row0 + r)) << 10) + (kt << 5) + (seg << 3);
        CP_ASYNC16(stg + (uint32_t)(r * 80 + seg * 16), src);
    }
    // B: 256 rows x 32 k x 2B = 16KB = 1024 x 16B (4 per thread)
    const int u0 = ng * 256;
    #pragma unroll
    for (int k = 0; k < 4; ++k) {
        int idx = tid + k * 256;
        int r = idx >> 2, seg = idx & 3;
        const __half* src = g_Bhi + (((size_t)(u0 + r)) << 10) + (kt << 5) + (seg << 3);
        CP_ASYNC16(stg + A_BYTES + (uint32_t)(r * 80 + seg * 16), src);
    }
}

__global__ __launch_bounds__(256, 1) void score_mma_kernel(const float* __restrict__ W_com,
                                                           const float* __restrict__ b_com,
                                                           const float* __restrict__ b_enc) {
    extern __shared__ char sm[];
    const uint32_t sbase = smem_to_u32(sm);
    float2* decw = reinterpret_cast<float2*>(sm + OFF_DECW);
    float* red   = reinterpret_cast<float*>(sm + OFF_RED);

    const int tid  = threadIdx.x;
    const int wid  = tid >> 5, lane = tid & 31;
    const int wm   = wid & 1;           // rows wm*64
    const int wn   = wid >> 1;          // cols wn*64 (0..3)
    const int row0 = blockIdx.x * 128;
    const int b    = row0 >> 11;

    // 3-deep prefetch while decw fills
    score_loads(0, tid, row0, sbase);
    CP_COMMIT();
    score_loads(1, tid, row0, sbase);
    CP_COMMIT();
    score_loads(2, tid, row0, sbase);
    CP_COMMIT();

    for (int i = tid; i < Udim; i += 256)
        decw[i] = make_float2(g_dec_p[b * Udim + i] + b_enc[i], W_com[i]);

    float rs[8];
    #pragma unroll
    for (int i = 0; i < 8; ++i) rs[i] = 0.f;
    float acc[4][8][4];
    const uint32_t lrow = (uint32_t)(lane & 15) * 80u + ((uint32_t)(lane >> 4) << 4);

    #pragma unroll 1
    for (int t = 0; t < 128; ++t) {
        const int kt = t & 31;
        if (kt == 0) {
            #pragma unroll
            for (int mi = 0; mi < 4; ++mi)
                #pragma unroll
                for (int nj = 0; nj < 8; ++nj)
                    #pragma unroll
                    for (int e = 0; e < 4; ++e) acc[mi][nj][e] = 0.f;
        }
        if (t < 126) { CP_WAIT2(); } else if (t == 126) { CP_WAIT1(); } else { CP_WAIT0(); }
        __syncthreads();
        if (t + 3 < 128) {
            score_loads(t + 3, tid, row0, sbase);
            CP_COMMIT();
        }

        const uint32_t sA = sbase + (uint32_t)(t & (NSTG - 1)) * STG_BYTES;
        const uint32_t sB = sA + A_BYTES;
        #pragma unroll
        for (int ks = 0; ks < 2; ++ks) {
            uint32_t ah[4][4];
            #pragma unroll
            for (int mi = 0; mi < 4; ++mi)
                ldsm4(ah[mi], sA + (uint32_t)(wm * 64 + mi * 16) * 80u + lrow +
                               (uint32_t)ks * 32u);
            #pragma unroll
            for (int p = 0; p < 4; ++p) {
                uint32_t bh[4];
                ldsm4(bh, sB + (uint32_t)(wn * 64 + p * 16) * 80u + lrow + (uint32_t)ks * 32u);
                #pragma unroll
                for (int mi = 0; mi < 4; ++mi) {
                    mma_f16(acc[mi][2 * p],     ah[mi], bh[0], bh[2]);
                    mma_f16(acc[mi][2 * p + 1], ah[mi], bh[1], bh[3]);
                }
            }
        }

        if (kt == 31) {
            // epilogue: x = enc_p + (dec_p + b_enc); rs += W_com * tanh(x)
            const int ng = t >> 5;
            #pragma unroll
            for (int mi = 0; mi < 4; ++mi) {
                #pragma unroll
                for (int nj = 0; nj < 8; ++nj) {
                    int u = ng * 256 + wn * 64 + nj * 8 + 2 * (lane & 3);
                    float2 w0 = decw[u];
                    float2 w1 = decw[u + 1];
                    rs[2 * mi] += w0.y * tanh_fast(acc[mi][nj][0] + w0.x) +
                                  w1.y * tanh_fast(acc[mi][nj][1] + w1.x);
                    rs[2 * mi + 1] += w0.y * tanh_fast(acc[mi][nj][2] + w0.x) +
                                      w1.y * tanh_fast(acc[mi][nj][3] + w1.x);
                }
            }
        }
    }

    // reduce the 4-lane quads (cols) that share a row
    #pragma unroll
    for (int i = 0; i < 8; ++i) {
        rs[i] += __shfl_xor_sync(0xffffffffu, rs[i], 1);
        rs[i] += __shfl_xor_sync(0xffffffffu, rs[i], 2);
    }
    if ((lane & 3) == 0) {
        #pragma unroll
        for (int mi = 0; mi < 4; ++mi)
            #pragma unroll
            for (int h = 0; h < 2; ++h) {
                int row = wm * 64 + mi * 16 + h * 8 + (lane >> 2);
                red[row * 4 + wn] = rs[2 * mi + h];
            }
    }
    __syncthreads();
    if (tid < 128)
        g_scores[row0 + tid] = red[tid * 4] + red[tid * 4 + 1] + red[tid * 4 + 2] +
                               red[tid * 4 + 3] + __ldg(&b_com[0]);
}

// ============================================================================
// Kernel 3: softmax over S per batch
// ============================================================================
__global__ __launch_bounds__(256) void softmax_kernel(float* __restrict__ attn_out) {
    __shared__ float sm[256];
    const int b = blockIdx.x;
    const int tid = threadIdx.x;
    float v[8];
    float mx = -3.4e38f;
    #pragma unroll
    for (int i = 0; i < 8; ++i) {
        v[i] = g_scores[b * Sdim + tid + i * 256];
        mx = fmaxf(mx, v[i]);
    }
    sm[tid] = mx;
    __syncthreads();
    for (int off = 128; off > 0; off >>= 1) {
        if (tid < off) sm[tid] = fmaxf(sm[tid], sm[tid + off]);
        __syncthreads();
    }
    const float m = sm[0];
    __syncthreads();
    float sum = 0.f;
    #pragma unroll
    for (int i = 0; i < 8; ++i) {
        v[i] = expf(v[i] - m);
        sum += v[i];
    }
    sm[tid] = sum;
    __syncthreads();
    for (int off = 128; off > 0; off >>= 1) {
        if (tid < off) sm[tid] += sm[tid + off];
        __syncthreads();
    }
    const float inv = 1.f / sm[0];
    #pragma unroll
    for (int i = 0; i < 8; ++i) attn_out[b * Sdim + tid + i * 256] = v[i] * inv;
}

// ============================================================================
// Kernel 4: weighted[b,d] = sum_s attn[b,s] * h_enc_fp16[b,s,d] (8 s-splits,
// reads the fp16 copy: half the traffic)
// ============================================================================
__global__ __launch_bounds__(256) void weighted_kernel(const float* __restrict__ attn) {
    const int b = blockIdx.x;
    const int d4 = threadIdx.x;          // 256 threads x 4 halves = 1024
    const int spl = blockIdx.y;
    const int s0 = spl * (Sdim / 8);
    const uint2* base =
        reinterpret_cast<const uint2*>(g_Ahi + (((size_t)b * Sdim + s0) << 10)) + d4;
    const float* av = attn + b * Sdim + s0;
    float4 acc = make_float4(0.f, 0.f, 0.f, 0.f);
    #pragma unroll 4
    for (int s = 0; s < Sdim / 8; ++s) {
        float a = __ldg(av + s);
        uint2 v = base[(size_t)s * (Ddim / 4)];
        float2 f01 = __half22float2(*reinterpret_cast<__half2*>(&v.x));
        float2 f23 = __half22float2(*reinterpret_cast<__half2*>(&v.y));
        acc.x = fmaf(a, f01.x, acc.x);
        acc.y = fmaf(a, f01.y, acc.y);
        acc.z = fmaf(a, f23.x, acc.z);
        acc.w = fmaf(a, f23.y, acc.w);
    }
    *reinterpret_cast<float4*>(g_wpart + (size_t)(spl * Bdim + b) * Ddim + d4 * 4) = acc;
}

// ============================================================================
// Kernel 5: context[b,u] = b_enc[u] + sum_d weighted[b,d] * W_enc[d,u]
// ============================================================================
__global__ __launch_bounds__(256) void context_kernel(const float* __restrict__ W_enc,
                                                      const float* __restrict__ b_enc,
                                                      float* __restrict__ out_ctx) {
    __shared__ float wv[Ddim];
    const int b = blockIdx.x;
    const int u = blockIdx.y * 256 + threadIdx.x;
    for (int d = threadIdx.x; d < Ddim; d += 256) {
        float s = 0.f;
        #pragma unroll
        for (int p = 0; p < 8; ++p) s += g_wpart[(p * Bdim + b) * Ddim + d];
        wv[d] = s;
    }
    __syncthreads();
    float acc = b_enc[u];
    #pragma unroll 8
    for (int d = 0; d < Ddim; ++d) acc = fmaf(wv[d], W_enc[d * Udim + u], acc);
    out_ctx[b * Udim + u] = acc;
}

// ============================================================================
extern "C" void kernel_launch(void* const* d_in, const int* in_sizes, int n_in,
                              void* d_out, int out_size) {
    const float* h_enc = (const float*)d_in[0];
    const float* h_dec = (const float*)d_in[1];
    const float* W_enc = (const float*)d_in[2];
    const float* b_enc = (const float*)d_in[3];
    const float* W_dec = (const float*)d_in[4];
    const float* b_dec = (const float*)d_in[5];
    const float* W_com = (const float*)d_in[6];
    const float* b_com = (const float*)d_in[7];

    float* out = (float*)d_out;
    float* out_ctx = out;                 // [B,U]
    float* out_attn = out + Bdim * Udim;  // [B,S,1]

    cudaFuncSetAttribute(score_mma_kernel, cudaFuncAttributeMaxDynamicSharedMemorySize,
                         SMEM_SCORE);

    conv_h_kernel<<<(BS * Ddim) / (256 * 4), 256>>>(h_enc);
    conv_w_kernel<<<dim3(Udim / 32, Ddim / 32), dim3(32, 8)>>>(W_enc);
    decp_kernel<<<dim3(Bdim, Udim / 256), 256>>>(h_dec, W_dec, b_dec);
    score_mma_kernel<<<BS / 128, 256, SMEM_SCORE>>>(W_com, b_com, b_enc);
    softmax_kernel<<<Bdim, 256>>>(out_attn);
    weighted_kernel<<<dim3(Bdim, 8), 256>>>(out_attn);
    context_kernel<<<dim3(Bdim, Udim / 256), 256>>>(W_enc, b_enc, out_ctx);
}

// round 14
// speedup vs baseline: 4.2456x; 1.0223x over previous
#include <cuda_runtime.h>
#include <cuda_fp16.h>
#include <math.h>
#include <stdint.h>

// Problem dims (fixed per reference)
#define Bdim 32
#define Sdim 2048
#define Ddim 1024
#define Udim 1024
#define BS   (Bdim * Sdim)   // 65536 rows of the big GEMM

// ---- device scratch (no cudaMalloc allowed) ----
__device__ float g_dec_p[Bdim * Udim];            // [B,U]
__device__ float g_scores[Bdim * Sdim];           // [B,S]
__device__ float g_wpart[8 * Bdim * Ddim];        // s-split partials of attn-weighted h_enc
__device__ __half g_Ahi[(size_t)BS * Ddim];       // h_enc fp16 (128MB)
__device__ __half g_Bhi[(size_t)Udim * Ddim];     // W_enc^T fp16 [u][d]

// ============================================================================
// PTX helpers (portable sm_80-level ISA: cp.async / ldmatrix / mma.sync)
// ============================================================================
__device__ __forceinline__ uint32_t smem_to_u32(const void* p) {
    uint32_t a;
    asm("{ .reg .u64 t; cvta.to.shared.u64 t, %1; cvt.u32.u64 %0, t; }" : "=r"(a) : "l"(p));
    return a;
}
#define CP_ASYNC16(dst, src) \
    asm volatile("cp.async.cg.shared.global [%0], [%1], 16;" :: "r"(dst), "l"(src) : "memory")
#define CP_COMMIT() asm volatile("cp.async.commit_group;" ::: "memory")
#define CP_WAIT2()  asm volatile("cp.async.wait_group 2;" ::: "memory")
#define CP_WAIT1()  asm volatile("cp.async.wait_group 1;" ::: "memory")
#define CP_WAIT0()  asm volatile("cp.async.wait_group 0;" ::: "memory")

__device__ __forceinline__ void ldsm4(uint32_t* r, uint32_t addr) {
    asm volatile("ldmatrix.sync.aligned.m8n8.x4.shared.b16 {%0,%1,%2,%3}, [%4];"
                 : "=r"(r[0]), "=r"(r[1]), "=r"(r[2]), "=r"(r[3]) : "r"(addr));
}
// D(f32) += A(f16,4regs) * B(f16,2regs)   m16n8k16 row.col
__device__ __forceinline__ void mma_f16(float* d, const uint32_t* a, uint32_t b0, uint32_t b1) {
    asm volatile(
        "mma.sync.aligned.m16n8k16.row.col.f32.f16.f16.f32 "
        "{%0,%1,%2,%3}, {%4,%5,%6,%7}, {%8,%9}, {%0,%1,%2,%3};"
        : "+f"(d[0]), "+f"(d[1]), "+f"(d[2]), "+f"(d[3])
        : "r"(a[0]), "r"(a[1]), "r"(a[2]), "r"(a[3]), "r"(b0), "r"(b1));
}

// fast tanh: 1 - 2/(e^{2x}+1). MUFU.EX2 + MUFU.RCP, ~1e-6 abs err.
__device__ __forceinline__ float tanh_fast(float x) {
    float e = __expf(2.0f * x);
    return 1.0f - __fdividef(2.0f, e + 1.0f);
}

// ============================================================================
// Kernel 0a: convert h_enc -> fp16 (same layout)
// ============================================================================
__global__ __launch_bounds__(256) void conv_h_kernel(const float* __restrict__ src) {
    size_t i = ((size_t)blockIdx.x * 256 + threadIdx.x) * 4;
    float4 v = *reinterpret_cast<const float4*>(src + i);
    *reinterpret_cast<__half2*>(g_Ahi + i)     = __floats2half2_rn(v.x, v.y);
    *reinterpret_cast<__half2*>(g_Ahi + i + 2) = __floats2half2_rn(v.z, v.w);
}

// ============================================================================
// Kernel 0b: W_enc [D,U] -> transposed fp16 [U,D]
// ============================================================================
__global__ __launch_bounds__(256) void conv_w_kernel(const float* __restrict__ W) {
    __shared__ float s[32][33];
    int tx = threadIdx.x, ty = threadIdx.y;     // 32 x 8
    int u0 = blockIdx.x * 32, d0 = blockIdx.y * 32;
    #pragma unroll
    for (int k = 0; k < 4; ++k)
        s[ty + k * 8][tx] = W[(size_t)(d0 + ty + k * 8) * Udim + u0 + tx];
    __syncthreads();
    #pragma unroll
    for (int k = 0; k < 4; ++k) {
        float v = s[tx][ty + k * 8];
        g_Bhi[(size_t)(u0 + ty + k * 8) * Ddim + d0 + tx] = __float2half_rn(v);
    }
}

// ============================================================================
// Kernel 1: dec_p[b,u] = b_dec[u] + sum_d h_dec[b,d] * W_dec[d,u]
// ============================================================================
__global__ __launch_bounds__(256) void decp_kernel(const float* __restrict__ h_dec,
                                                   const float* __restrict__ W_dec,
                                                   const float* __restrict__ b_dec) {
    __shared__ float hv[Ddim];
    const int b = blockIdx.x;
    const int u = blockIdx.y * 256 + threadIdx.x;
    for (int d = threadIdx.x; d < Ddim; d += 256) hv[d] = h_dec[b * Ddim + d];
    __syncthreads();
    float acc = b_dec[u];
    #pragma unroll 8
    for (int d = 0; d < Ddim; ++d) acc = fmaf(hv[d], W_dec[d * Udim + u], acc);
    g_dec_p[b * Udim + u] = acc;
}

// ============================================================================
// Kernel 2: score GEMM via mma.sync fp16 + fused tanh/W_com epilogue.
// CTA tile 128 x 256 (4 n-groups over U). 8 warps of 64x64 (wm=wid&1, wn=wid>>1).
// BK=32. Flat 128-iter mainloop, 4-stage cp.async (3-deep), ONE barrier/iter.
// All 16 fragments (8 A-ldsm + 8 B-ldsm) prefetched to registers BEFORE the
// 64 MMAs -> no LDSM->HMMA RAW convoys.
// ============================================================================
#define A_BYTES  10240u                 // 128 rows * 80B
#define B_BYTES  20480u                 // 256 rows * 80B
#define STG_BYTES (A_BYTES + B_BYTES)   // 30720
#define NSTG 4
#define OFF_DECW (NSTG * STG_BYTES)     // 122880: float2[1024] = 8192
#define OFF_RED  (OFF_DECW + 8192u)     // float[128][4] = 2048
#define SMEM_SCORE (OFF_RED + 2048u)    // 133120

__device__ __forceinline__ void score_loads(int t, int tid, int row0, uint32_t sbase) {
    const int kt = t & 31, ng = t >> 5;
    const uint32_t stg = sbase + (uint32_t)(t & (NSTG - 1)) * STG_BYTES;
    // A: 128 rows x 32 k x 2B = 8KB = 512 x 16B  (2 per thread)
    #pragma unroll
    for (int k = 0; k < 2; ++k) {
        int idx = tid + k * 256;
        int r = idx >> 2, seg = idx & 3;
        const __half* src = g_Ahi + (((size_t)(row0 + r)) << 10) + (kt << 5) + (seg << 3);
        CP_ASYNC16(stg + (uint32_t)(r * 80 + seg * 16), src);
    }
    // B: 256 rows x 32 k x 2B = 16KB = 1024 x 16B (4 per thread)
    const int u0 = ng * 256;
    #pragma unroll
    for (int k = 0; k < 4; ++k) {
        int idx = tid + k * 256;
        int r = idx >> 2, seg = idx & 3;
        const __half* src = g_Bhi + (((size_t)(u0 + r)) << 10) + (kt << 5) + (seg << 3);
        CP_ASYNC16(stg + A_BYTES + (uint32_t)(r * 80 + seg * 16), src);
    }
}

__global__ __launch_bounds__(256, 1) void score_mma_kernel(const float* __restrict__ W_com,
                                                           const float* __restrict__ b_com,
                                                           const float* __restrict__ b_enc) {
    extern __shared__ char sm[];
    const uint32_t sbase = smem_to_u32(sm);
    float2* decw = reinterpret_cast<float2*>(sm + OFF_DECW);
    float* red   = reinterpret_cast<float*>(sm + OFF_RED);

    const int tid  = threadIdx.x;
    const int wid  = tid >> 5, lane = tid & 31;
    const int wm   = wid & 1;           // rows wm*64
    const int wn   = wid >> 1;          // cols wn*64 (0..3)
    const int row0 = blockIdx.x * 128;
    const int b    = row0 >> 11;

    // 3-deep prefetch while decw fills
    score_loads(0, tid, row0, sbase);
    CP_COMMIT();
    score_loads(1, tid, row0, sbase);
    CP_COMMIT();
    score_loads(2, tid, row0, sbase);
    CP_COMMIT();

    for (int i = tid; i < Udim; i += 256)
        decw[i] = make_float2(g_dec_p[b * Udim + i] + b_enc[i], W_com[i]);

    float rs[8];
    #pragma unroll
    for (int i = 0; i < 8; ++i) rs[i] = 0.f;
    float acc[4][8][4];
    const uint32_t lrow = (uint32_t)(lane & 15) * 80u + ((uint32_t)(lane >> 4) << 4);
    // loop-invariant per-warp smem bases (within a stage)
    const uint32_t aOff = (uint32_t)(wm * 64) * 80u + lrow;
    const uint32_t bOff = A_BYTES + (uint32_t)(wn * 64) * 80u + lrow;

    #pragma unroll 1
    for (int t = 0; t < 128; ++t) {
        const int kt = t & 31;
        if (kt == 0) {
            #pragma unroll
            for (int mi = 0; mi < 4; ++mi)
                #pragma unroll
                for (int nj = 0; nj < 8; ++nj)
                    #pragma unroll
                    for (int e = 0; e < 4; ++e) acc[mi][nj][e] = 0.f;
        }
        if (t < 126) { CP_WAIT2(); } else if (t == 126) { CP_WAIT1(); } else { CP_WAIT0(); }
        __syncthreads();
        if (t + 3 < 128) {
            score_loads(t + 3, tid, row0, sbase);
            CP_COMMIT();
        }

        const uint32_t stg = sbase + (uint32_t)(t & (NSTG - 1)) * STG_BYTES;
        // ---- prefetch ALL fragments for this BK=32 chunk ----
        uint32_t af[2][4][4];   // [ks][mi][4]
        uint32_t bf[2][4][4];   // [ks][p][4]
        #pragma unroll
        for (int ks = 0; ks < 2; ++ks)
            #pragma unroll
            for (int mi = 0; mi < 4; ++mi)
                ldsm4(af[ks][mi], stg + aOff + (uint32_t)(mi * 16) * 80u + (uint32_t)ks * 32u);
        #pragma unroll
        for (int ks = 0; ks < 2; ++ks)
            #pragma unroll
            for (int p = 0; p < 4; ++p)
                ldsm4(bf[ks][p], stg + bOff + (uint32_t)(p * 16) * 80u + (uint32_t)ks * 32u);
        // ---- stream 64 MMAs, all operands in registers ----
        #pragma unroll
        for (int ks = 0; ks < 2; ++ks)
            #pragma unroll
            for (int p = 0; p < 4; ++p)
                #pragma unroll
                for (int mi = 0; mi < 4; ++mi) {
                    mma_f16(acc[mi][2 * p],     af[ks][mi], bf[ks][p][0], bf[ks][p][2]);
                    mma_f16(acc[mi][2 * p + 1], af[ks][mi], bf[ks][p][1], bf[ks][p][3]);
                }

        if (kt == 31) {
            // epilogue: x = enc_p + (dec_p + b_enc); rs += W_com * tanh(x)
            const int ng = t >> 5;
            #pragma unroll
            for (int mi = 0; mi < 4; ++mi) {
                #pragma unroll
                for (int nj = 0; nj < 8; ++nj) {
                    int u = ng * 256 + wn * 64 + nj * 8 + 2 * (lane & 3);
                    float2 w0 = decw[u];
                    float2 w1 = decw[u + 1];
                    rs[2 * mi] += w0.y * tanh_fast(acc[mi][nj][0] + w0.x) +
                                  w1.y * tanh_fast(acc[mi][nj][1] + w1.x);
                    rs[2 * mi + 1] += w0.y * tanh_fast(acc[mi][nj][2] + w0.x) +
                                      w1.y * tanh_fast(acc[mi][nj][3] + w1.x);
                }
            }
        }
    }

    // reduce the 4-lane quads (cols) that share a row
    #pragma unroll
    for (int i = 0; i < 8; ++i) {
        rs[i] += __shfl_xor_sync(0xffffffffu, rs[i], 1);
        rs[i] += __shfl_xor_sync(0xffffffffu, rs[i], 2);
    }
    if ((lane & 3) == 0) {
        #pragma unroll
        for (int mi = 0; mi < 4; ++mi)
            #pragma unroll
            for (int h = 0; h < 2; ++h) {
                int row = wm * 64 + mi * 16 + h * 8 + (lane >> 2);
                red[row * 4 + wn] = rs[2 * mi + h];
            }
    }
    __syncthreads();
    if (tid < 128)
        g_scores[row0 + tid] = red[tid * 4] + red[tid * 4 + 1] + red[tid * 4 + 2] +
                               red[tid * 4 + 3] + __ldg(&b_com[0]);
}

// ============================================================================
// Kernel 3: softmax over S per batch
// ============================================================================
__global__ __launch_bounds__(256) void softmax_kernel(float* __restrict__ attn_out) {
    __shared__ float sm[256];
    const int b = blockIdx.x;
    const int tid = threadIdx.x;
    float v[8];
    float mx = -3.4e38f;
    #pragma unroll
    for (int i = 0; i < 8; ++i) {
        v[i] = g_scores[b * Sdim + tid + i * 256];
        mx = fmaxf(mx, v[i]);
    }
    sm[tid] = mx;
    __syncthreads();
    for (int off = 128; off > 0; off >>= 1) {
        if (tid < off) sm[tid] = fmaxf(sm[tid], sm[tid + off]);
        __syncthreads();
    }
    const float m = sm[0];
    __syncthreads();
    float sum = 0.f;
    #pragma unroll
    for (int i = 0; i < 8; ++i) {
        v[i] = expf(v[i] - m);
        sum += v[i];
    }
    sm[tid] = sum;
    __syncthreads();
    for (int off = 128; off > 0; off >>= 1) {
        if (tid < off) sm[tid] += sm[tid + off];
        __syncthreads();
    }
    const float inv = 1.f / sm[0];
    #pragma unroll
    for (int i = 0; i < 8; ++i) attn_out[b * Sdim + tid + i * 256] = v[i] * inv;
}

// ============================================================================
// Kernel 4: weighted[b,d] = sum_s attn[b,s] * h_enc_fp16[b,s,d] (8 s-splits,
// reads the fp16 copy: half the traffic)
// ============================================================================
__global__ __launch_bounds__(256) void weighted_kernel(const float* __restrict__ attn) {
    const int b = blockIdx.x;
    const int d4 = threadIdx.x;          // 256 threads x 4 halves = 1024
    const int spl = blockIdx.y;
    const int s0 = spl * (Sdim / 8);
    const uint2* base =
        reinterpret_cast<const uint2*>(g_Ahi + (((size_t)b * Sdim + s0) << 10)) + d4;
    const float* av = attn + b * Sdim + s0;
    float4 acc = make_float4(0.f, 0.f, 0.f, 0.f);
    #pragma unroll 4
    for (int s = 0; s < Sdim / 8; ++s) {
        float a = __ldg(av + s);
        uint2 v = base[(size_t)s * (Ddim / 4)];
        float2 f01 = __half22float2(*reinterpret_cast<__half2*>(&v.x));
        float2 f23 = __half22float2(*reinterpret_cast<__half2*>(&v.y));
        acc.x = fmaf(a, f01.x, acc.x);
        acc.y = fmaf(a, f01.y, acc.y);
        acc.z = fmaf(a, f23.x, acc.z);
        acc.w = fmaf(a, f23.y, acc.w);
    }
    *reinterpret_cast<float4*>(g_wpart + (size_t)(spl * Bdim + b) * Ddim + d4 * 4) = acc;
}

// ============================================================================
// Kernel 5: context[b,u] = b_enc[u] + sum_d weighted[b,d] * W_enc[d,u]
// ============================================================================
__global__ __launch_bounds__(256) void context_kernel(const float* __restrict__ W_enc,
                                                      const float* __restrict__ b_enc,
                                                      float* __restrict__ out_ctx) {
    __shared__ float wv[Ddim];
    const int b = blockIdx.x;
    const int u = blockIdx.y * 256 + threadIdx.x;
    for (int d = threadIdx.x; d < Ddim; d += 256) {
        float s = 0.f;
        #pragma unroll
        for (int p = 0; p < 8; ++p) s += g_wpart[(p * Bdim + b) * Ddim + d];
        wv[d] = s;
    }
    __syncthreads();
    float acc = b_enc[u];
    #pragma unroll 8
    for (int d = 0; d < Ddim; ++d) acc = fmaf(wv[d], W_enc[d * Udim + u], acc);
    out_ctx[b * Udim + u] = acc;
}

// ============================================================================
extern "C" void kernel_launch(void* const* d_in, const int* in_sizes, int n_in,
                              void* d_out, int out_size) {
    const float* h_enc = (const float*)d_in[0];
    const float* h_dec = (const float*)d_in[1];
    const float* W_enc = (const float*)d_in[2];
    const float* b_enc = (const float*)d_in[3];
    const float* W_dec = (const float*)d_in[4];
    const float* b_dec = (const float*)d_in[5];
    const float* W_com = (const float*)d_in[6];
    const float* b_com = (const float*)d_in[7];

    float* out = (float*)d_out;
    float* out_ctx = out;                 // [B,U]
    float* out_attn = out + Bdim * Udim;  // [B,S,1]

    cudaFuncSetAttribute(score_mma_kernel, cudaFuncAttributeMaxDynamicSharedMemorySize,
                         SMEM_SCORE);

    conv_h_kernel<<<(BS * Ddim) / (256 * 4), 256>>>(h_enc);
    conv_w_kernel<<<dim3(Udim / 32, Ddim / 32), dim3(32, 8)>>>(W_enc);
    decp_kernel<<<dim3(Bdim, Udim / 256), 256>>>(h_dec, W_dec, b_dec);
    score_mma_kernel<<<BS / 128, 256, SMEM_SCORE>>>(W_com, b_com, b_enc);
    softmax_kernel<<<Bdim, 256>>>(out_attn);
    weighted_kernel<<<dim3(Bdim, 8), 256>>>(out_attn);
    context_kernel<<<dim3(Bdim, Udim / 256), 256>>>(W_enc, b_enc, out_ctx);
}

// round 16
// speedup vs baseline: 4.3248x; 1.0186x over previous
#include <cuda_runtime.h>
#include <cuda_fp16.h>
#include <math.h>
#include <stdint.h>

// Problem dims (fixed per reference)
#define Bdim 32
#define Sdim 2048
#define Ddim 1024
#define Udim 1024
#define BS   (Bdim * Sdim)   // 65536 rows of the big GEMM

// ---- device scratch (no cudaMalloc allowed) ----
__device__ float g_dec_p[Bdim * Udim];            // [B,U]
__device__ float g_scores[Bdim * Sdim];           // [B,S]
__device__ float g_wpart[8 * Bdim * Ddim];        // s-split partials of attn-weighted h_enc
__device__ __half g_Ahi[(size_t)BS * Ddim];       // h_enc fp16 (128MB)
__device__ __half g_Bhi[(size_t)Udim * Ddim];     // W_enc^T fp16 [u][d]

// ============================================================================
// PTX helpers (portable sm_80-level ISA: cp.async / ldmatrix / mma.sync)
// ============================================================================
__device__ __forceinline__ uint32_t smem_to_u32(const void* p) {
    uint32_t a;
    asm("{ .reg .u64 t; cvta.to.shared.u64 t, %1; cvt.u32.u64 %0, t; }" : "=r"(a) : "l"(p));
    return a;
}
#define CP_ASYNC16(dst, src) \
    asm volatile("cp.async.cg.shared.global [%0], [%1], 16;" :: "r"(dst), "l"(src) : "memory")
#define CP_COMMIT() asm volatile("cp.async.commit_group;" ::: "memory")
#define CP_WAIT2()  asm volatile("cp.async.wait_group 2;" ::: "memory")
#define CP_WAIT1()  asm volatile("cp.async.wait_group 1;" ::: "memory")
#define CP_WAIT0()  asm volatile("cp.async.wait_group 0;" ::: "memory")

__device__ __forceinline__ void ldsm4(uint32_t* r, uint32_t addr) {
    asm volatile("ldmatrix.sync.aligned.m8n8.x4.shared.b16 {%0,%1,%2,%3}, [%4];"
                 : "=r"(r[0]), "=r"(r[1]), "=r"(r[2]), "=r"(r[3]) : "r"(addr));
}
// D(f32) += A(f16,4regs) * B(f16,2regs)   m16n8k16 row.col
__device__ __forceinline__ void mma_f16(float* d, const uint32_t* a, uint32_t b0, uint32_t b1) {
    asm volatile(
        "mma.sync.aligned.m16n8k16.row.col.f32.f16.f16.f32 "
        "{%0,%1,%2,%3}, {%4,%5,%6,%7}, {%8,%9}, {%0,%1,%2,%3};"
        : "+f"(d[0]), "+f"(d[1]), "+f"(d[2]), "+f"(d[3])
        : "r"(a[0]), "r"(a[1]), "r"(a[2]), "r"(a[3]), "r"(b0), "r"(b1));
}

// fast tanh: 1 - 2/(e^{2x}+1). MUFU.EX2 + MUFU.RCP, ~1e-6 abs err.
__device__ __forceinline__ float tanh_fast(float x) {
    float e = __expf(2.0f * x);
    return 1.0f - __fdividef(2.0f, e + 1.0f);
}

// ============================================================================
// Kernel 0a: convert h_enc -> fp16 (same layout)
// ============================================================================
__global__ __launch_bounds__(256) void conv_h_kernel(const float* __restrict__ src) {
    size_t i = ((size_t)blockIdx.x * 256 + threadIdx.x) * 4;
    float4 v = *reinterpret_cast<const float4*>(src + i);
    *reinterpret_cast<__half2*>(g_Ahi + i)     = __floats2half2_rn(v.x, v.y);
    *reinterpret_cast<__half2*>(g_Ahi + i + 2) = __floats2half2_rn(v.z, v.w);
}

// ============================================================================
// Kernel 0b: W_enc [D,U] -> transposed fp16 [U,D]
// ============================================================================
__global__ __launch_bounds__(256) void conv_w_kernel(const float* __restrict__ W) {
    __shared__ float s[32][33];
    int tx = threadIdx.x, ty = threadIdx.y;     // 32 x 8
    int u0 = blockIdx.x * 32, d0 = blockIdx.y * 32;
    #pragma unroll
    for (int k = 0; k < 4; ++k)
        s[ty + k * 8][tx] = W[(size_t)(d0 + ty + k * 8) * Udim + u0 + tx];
    __syncthreads();
    #pragma unroll
    for (int k = 0; k < 4; ++k) {
        float v = s[tx][ty + k * 8];
        g_Bhi[(size_t)(u0 + ty + k * 8) * Ddim + d0 + tx] = __float2half_rn(v);
    }
}

// ============================================================================
// Kernel 1: dec_p[b,u] = b_dec[u] + sum_d h_dec[b,d] * W_dec[d,u]
// ============================================================================
__global__ __launch_bounds__(256) void decp_kernel(const float* __restrict__ h_dec,
                                                   const float* __restrict__ W_dec,
                                                   const float* __restrict__ b_dec) {
    __shared__ float hv[Ddim];
    const int b = blockIdx.x;
    const int u = blockIdx.y * 256 + threadIdx.x;
    for (int d = threadIdx.x; d < Ddim; d += 256) hv[d] = h_dec[b * Ddim + d];
    __syncthreads();
    float acc = b_dec[u];
    #pragma unroll 8
    for (int d = 0; d < Ddim; ++d) acc = fmaf(hv[d], W_dec[d * Udim + u], acc);
    g_dec_p[b * Udim + u] = acc;
}

// ============================================================================
// Kernel 2: score GEMM via mma.sync fp16 + fused tanh/W_com epilogue.
// CTA tile 128 x 256 (4 n-groups over U). 8 warps of 64x64 (wm=wid&1, wn=wid>>1).
// BK=32. Flat 128-iter mainloop, 4-stage cp.async (3-deep), ONE barrier/iter.
// All load addresses hoisted out of the loop; LDSM/MMA explicitly interleaved.
// ============================================================================
#define A_BYTES  10240u                 // 128 rows * 80B
#define B_BYTES  20480u                 // 256 rows * 80B
#define STG_BYTES (A_BYTES + B_BYTES)   // 30720
#define NSTG 4
#define OFF_DECW (NSTG * STG_BYTES)     // 122880: float2[1024] = 8192
#define OFF_RED  (OFF_DECW + 8192u)     // float[128][4] = 2048
#define SMEM_SCORE (OFF_RED + 2048u)    // 133120

struct LoadCtx {
    const __half* srcA[2];   // per-thread A base (row0,r,seg folded in)
    const __half* srcB[4];   // per-thread B base (r,seg folded in)
    uint32_t dstA[2];        // smem offsets relative to stage base
    uint32_t dstB[4];
};

__device__ __forceinline__ void score_loads(const LoadCtx& c, int t, uint32_t sbase) {
    const uint32_t stg = sbase + (uint32_t)(t & (NSTG - 1)) * STG_BYTES;
    const uint32_t aoff = (uint32_t)((t & 31) << 5);               // kt*32 elements
    const uint32_t boff = (uint32_t)((t >> 5) << 18) | aoff;       // ng*256*1024 + kt*32
    #pragma unroll
    for (int k = 0; k < 2; ++k) CP_ASYNC16(stg + c.dstA[k], c.srcA[k] + aoff);
    #pragma unroll
    for (int k = 0; k < 4; ++k) CP_ASYNC16(stg + c.dstB[k], c.srcB[k] + boff);
}

__global__ __launch_bounds__(256, 1) void score_mma_kernel(const float* __restrict__ W_com,
                                                           const float* __restrict__ b_com,
                                                           const float* __restrict__ b_enc) {
    extern __shared__ char sm[];
    const uint32_t sbase = smem_to_u32(sm);
    float2* decw = reinterpret_cast<float2*>(sm + OFF_DECW);
    float* red   = reinterpret_cast<float*>(sm + OFF_RED);

    const int tid  = threadIdx.x;
    const int wid  = tid >> 5, lane = tid & 31;
    const int wm   = wid & 1;           // rows wm*64
    const int wn   = wid >> 1;          // cols wn*64 (0..3)
    const int row0 = blockIdx.x * 128;
    const int b    = row0 >> 11;

    // ---- hoisted per-thread load addressing ----
    LoadCtx c;
    #pragma unroll
    for (int k = 0; k < 2; ++k) {
        int idx = tid + k * 256;
        int r = idx >> 2, seg = idx & 3;       // r: 0..127 (A has 128 rows)
        c.srcA[k] = g_Ahi + (((size_t)(row0 + r)) << 10) + (seg << 3);
        c.dstA[k] = (uint32_t)(r * 80 + seg * 16);
    }
    #pragma unroll
    for (int k = 0; k < 4; ++k) {
        int idx = tid + k * 256;
        int r = idx >> 2, seg = idx & 3;       // r: 0..255 (B has 256 rows!)
        c.srcB[k] = g_Bhi + (((size_t)r) << 10) + (seg << 3);
        c.dstB[k] = A_BYTES + (uint32_t)(r * 80 + seg * 16);
    }

    // 3-deep prefetch while decw fills
    score_loads(c, 0, sbase);
    CP_COMMIT();
    score_loads(c, 1, sbase);
    CP_COMMIT();
    score_loads(c, 2, sbase);
    CP_COMMIT();

    for (int i = tid; i < Udim; i += 256)
        decw[i] = make_float2(g_dec_p[b * Udim + i] + b_enc[i], W_com[i]);

    float rs[8];
    #pragma unroll
    for (int i = 0; i < 8; ++i) rs[i] = 0.f;
    float acc[4][8][4];
    const uint32_t lrow = (uint32_t)(lane & 15) * 80u + ((uint32_t)(lane >> 4) << 4);
    const uint32_t aOff = (uint32_t)(wm * 64) * 80u + lrow;
    const uint32_t bOff = A_BYTES + (uint32_t)(wn * 64) * 80u + lrow;

    #pragma unroll 1
    for (int t = 0; t < 128; ++t) {
        const int kt = t & 31;
        if (kt == 0) {
            #pragma unroll
            for (int mi = 0; mi < 4; ++mi)
                #pragma unroll
                for (int nj = 0; nj < 8; ++nj)
                    #pragma unroll
                    for (int e = 0; e < 4; ++e) acc[mi][nj][e] = 0.f;
        }
        if (t < 126) { CP_WAIT2(); } else if (t == 126) { CP_WAIT1(); } else { CP_WAIT0(); }
        __syncthreads();
        if (t + 3 < 128) {
            score_loads(c, t + 3, sbase);
            CP_COMMIT();
        }

        const uint32_t stg = sbase + (uint32_t)(t & (NSTG - 1)) * STG_BYTES;
        const uint32_t sA = stg + aOff;
        const uint32_t sB = stg + bOff;
        uint32_t af[2][4][4];   // [ks][mi][4]
        uint32_t bf[2][4][4];   // [ks][p][4]
        // ---- ks0 fragments ----
        #pragma unroll
        for (int mi = 0; mi < 4; ++mi) ldsm4(af[0][mi], sA + (uint32_t)(mi * 16) * 80u);
        #pragma unroll
        for (int p = 0; p < 4; ++p)   ldsm4(bf[0][p], sB + (uint32_t)(p * 16) * 80u);
        // ---- p=0 of ks0 ----
        #pragma unroll
        for (int mi = 0; mi < 4; ++mi) {
            mma_f16(acc[mi][0], af[0][mi], bf[0][0][0], bf[0][0][2]);
            mma_f16(acc[mi][1], af[0][mi], bf[0][0][1], bf[0][0][3]);
        }
        // ---- A ks1 fragments overlap with p=1 ----
        #pragma unroll
        for (int mi = 0; mi < 4; ++mi) ldsm4(af[1][mi], sA + (uint32_t)(mi * 16) * 80u + 32u);
        #pragma unroll
        for (int mi = 0; mi < 4; ++mi) {
            mma_f16(acc[mi][2], af[0][mi], bf[0][1][0], bf[0][1][2]);
            mma_f16(acc[mi][3], af[0][mi], bf[0][1][1], bf[0][1][3]);
        }
        // ---- B ks1 fragments overlap with p=2,3 ----
        #pragma unroll
        for (int p = 0; p < 4; ++p)   ldsm4(bf[1][p], sB + (uint32_t)(p * 16) * 80u + 32u);
        #pragma unroll
        for (int p = 2; p < 4; ++p)
            #pragma unroll
            for (int mi = 0; mi < 4; ++mi) {
                mma_f16(acc[mi][2 * p],     af[0][mi], bf[0][p][0], bf[0][p][2]);
                mma_f16(acc[mi][2 * p + 1], af[0][mi], bf[0][p][1], bf[0][p][3]);
            }
        // ---- all of ks1 ----
        #pragma unroll
        for (int p = 0; p < 4; ++p)
            #pragma unroll
            for (int mi = 0; mi < 4; ++mi) {
                mma_f16(acc[mi][2 * p],     af[1][mi], bf[1][p][0], bf[1][p][2]);
                mma_f16(acc[mi][2 * p + 1], af[1][mi], bf[1][p][1], bf[1][p][3]);
            }

        if (kt == 31) {
            // epilogue: x = enc_p + (dec_p + b_enc); rs += W_com * tanh(x)
            const int ng = t >> 5;
            #pragma unroll
            for (int mi = 0; mi < 4; ++mi) {
                #pragma unroll
                for (int nj = 0; nj < 8; ++nj) {
                    int u = ng * 256 + wn * 64 + nj * 8 + 2 * (lane & 3);
                    float2 w0 = decw[u];
                    float2 w1 = decw[u + 1];
                    rs[2 * mi] += w0.y * tanh_fast(acc[mi][nj][0] + w0.x) +
                                  w1.y * tanh_fast(acc[mi][nj][1] + w1.x);
                    rs[2 * mi + 1] += w0.y * tanh_fast(acc[mi][nj][2] + w0.x) +
                                      w1.y * tanh_fast(acc[mi][nj][3] + w1.x);
                }
            }
        }
    }

    // reduce the 4-lane quads (cols) that share a row
    #pragma unroll
    for (int i = 0; i < 8; ++i) {
        rs[i] += __shfl_xor_sync(0xffffffffu, rs[i], 1);
        rs[i] += __shfl_xor_sync(0xffffffffu, rs[i], 2);
    }
    if ((lane & 3) == 0) {
        #pragma unroll
        for (int mi = 0; mi < 4; ++mi)
            #pragma unroll
            for (int h = 0; h < 2; ++h) {
                int row = wm * 64 + mi * 16 + h * 8 + (lane >> 2);
                red[row * 4 + wn] = rs[2 * mi + h];
            }
    }
    __syncthreads();
    if (tid < 128)
        g_scores[row0 + tid] = red[tid * 4] + red[tid * 4 + 1] + red[tid * 4 + 2] +
                               red[tid * 4 + 3] + __ldg(&b_com[0]);
}

// ============================================================================
// Kernel 3: softmax over S per batch
// ============================================================================
__global__ __launch_bounds__(256) void softmax_kernel(float* __restrict__ attn_out) {
    __shared__ float sm[256];
    const int b = blockIdx.x;
    const int tid = threadIdx.x;
    float v[8];
    float mx = -3.4e38f;
    #pragma unroll
    for (int i = 0; i < 8; ++i) {
        v[i] = g_scores[b * Sdim + tid + i * 256];
        mx = fmaxf(mx, v[i]);
    }
    sm[tid] = mx;
    __syncthreads();
    for (int off = 128; off > 0; off >>= 1) {
        if (tid < off) sm[tid] = fmaxf(sm[tid], sm[tid + off]);
        __syncthreads();
    }
    const float m = sm[0];
    __syncthreads();
    float sum = 0.f;
    #pragma unroll
    for (int i = 0; i < 8; ++i) {
        v[i] = expf(v[i] - m);
        sum += v[i];
    }
    sm[tid] = sum;
    __syncthreads();
    for (int off = 128; off > 0; off >>= 1) {
        if (tid < off) sm[tid] += sm[tid + off];
        __syncthreads();
    }
    const float inv = 1.f / sm[0];
    #pragma unroll
    for (int i = 0; i < 8; ++i) attn_out[b * Sdim + tid + i * 256] = v[i] * inv;
}

// ============================================================================
// Kernel 4: weighted[b,d] = sum_s attn[b,s] * h_enc_fp16[b,s,d] (8 s-splits,
// reads the fp16 copy: half the traffic)
// ============================================================================
__global__ __launch_bounds__(256) void weighted_kernel(const float* __restrict__ attn) {
    const int b = blockIdx.x;
    const int d4 = threadIdx.x;          // 256 threads x 4 halves = 1024
    const int spl = blockIdx.y;
    const int s0 = spl * (Sdim / 8);
    const uint2* base =
        reinterpret_cast<const uint2*>(g_Ahi + (((size_t)b * Sdim + s0) << 10)) + d4;
    const float* av = attn + b * Sdim + s0;
    float4 acc = make_float4(0.f, 0.f, 0.f, 0.f);
    #pragma unroll 4
    for (int s = 0; s < Sdim / 8; ++s) {
        float a = __ldg(av + s);
        uint2 v = base[(size_t)s * (Ddim / 4)];
        float2 f01 = __half22float2(*reinterpret_cast<__half2*>(&v.x));
        float2 f23 = __half22float2(*reinterpret_cast<__half2*>(&v.y));
        acc.x = fmaf(a, f01.x, acc.x);
        acc.y = fmaf(a, f01.y, acc.y);
        acc.z = fmaf(a, f23.x, acc.z);
        acc.w = fmaf(a, f23.y, acc.w);
    }
    *reinterpret_cast<float4*>(g_wpart + (size_t)(spl * Bdim + b) * Ddim + d4 * 4) = acc;
}

// ============================================================================
// Kernel 5: context[b,u] = b_enc[u] + sum_d weighted[b,d] * W_enc[d,u]
// ============================================================================
__global__ __launch_bounds__(256) void context_kernel(const float* __restrict__ W_enc,
                                                      const float* __restrict__ b_enc,
                                                      float* __restrict__ out_ctx) {
    __shared__ float wv[Ddim];
    const int b = blockIdx.x;
    const int u = blockIdx.y * 256 + threadIdx.x;
    for (int d = threadIdx.x; d < Ddim; d += 256) {
        float s = 0.f;
        #pragma unroll
        for (int p = 0; p < 8; ++p) s += g_wpart[(p * Bdim + b) * Ddim + d];
        wv[d] = s;
    }
    __syncthreads();
    float acc = b_enc[u];
    #pragma unroll 8
    for (int d = 0; d < Ddim; ++d) acc = fmaf(wv[d], W_enc[d * Udim + u], acc);
    out_ctx[b * Udim + u] = acc;
}

// ============================================================================
extern "C" void kernel_launch(void* const* d_in, const int* in_sizes, int n_in,
                              void* d_out, int out_size) {
    const float* h_enc = (const float*)d_in[0];
    const float* h_dec = (const float*)d_in[1];
    const float* W_enc = (const float*)d_in[2];
    const float* b_enc = (const float*)d_in[3];
    const float* W_dec = (const float*)d_in[4];
    const float* b_dec = (const float*)d_in[5];
    const float* W_com = (const float*)d_in[6];
    const float* b_com = (const float*)d_in[7];

    float* out = (float*)d_out;
    float* out_ctx = out;                 // [B,U]
    float* out_attn = out + Bdim * Udim;  // [B,S,1]

    cudaFuncSetAttribute(score_mma_kernel, cudaFuncAttributeMaxDynamicSharedMemorySize,
                         SMEM_SCORE);

    conv_h_kernel<<<(BS * Ddim) / (256 * 4), 256>>>(h_enc);
    conv_w_kernel<<<dim3(Udim / 32, Ddim / 32), dim3(32, 8)>>>(W_enc);
    decp_kernel<<<dim3(Bdim, Udim / 256), 256>>>(h_dec, W_dec, b_dec);
    score_mma_kernel<<<BS / 128, 256, SMEM_SCORE>>>(W_com, b_com, b_enc);
    softmax_kernel<<<Bdim, 256>>>(out_attn);
    weighted_kernel<<<dim3(Bdim, 8), 256>>>(out_attn);
    context_kernel<<<dim3(Bdim, Udim / 256), 256>>>(W_enc, b_enc, out_ctx);
}